// round 1
// baseline (speedup 1.0000x reference)
#include <cuda_runtime.h>
#include <math.h>

// Problem constants
#define B_   2
#define L_   2048
#define H_   1024
#define NH_  16
#define D_   64
#define M_   (B_ * L_)      // 4096
#define BH_  (B_ * NH_)     // 32

// Scratch (device globals; no allocation allowed)
__device__ float g_Q[(size_t)BH_ * L_ * D_];   // [B*NH, L, D], pre-scaled by D^-0.5
__device__ float g_K[(size_t)BH_ * L_ * D_];   // [B*NH, L, D]
__device__ float g_V[(size_t)BH_ * L_ * D_];   // [B*NH, L, D]
__device__ float g_T[(size_t)M_ * H_];         // attention output, [B*L, H]

// ---------------------------------------------------------------------------
// SGEMM: C[M,N] = A[M,K] @ W[K,N]  (row-major)
// mode 0: plain row-major store (scaled)
// mode 1: head-split store into [B*NH, L, D] (scaled)
// BM=BN=128, BK=8, 256 threads, 8x8 micro-tile (split 4+4 layout)
// ---------------------------------------------------------------------------
__global__ __launch_bounds__(256) void sgemm_kernel(
    const float* __restrict__ A, const float* __restrict__ W,
    float* __restrict__ C, int M, int K, int N, int mode, float scale)
{
    __shared__ float As[8][128];
    __shared__ float Bs[8][128];

    const int tid  = threadIdx.x;
    const int bm   = blockIdx.y * 128;
    const int bn   = blockIdx.x * 128;
    const int arow = tid >> 1;
    const int acol = (tid & 1) << 2;
    const int brow = tid >> 5;
    const int bcol = (tid & 31) << 2;
    const int tr   = tid >> 4;   // 0..15
    const int tc   = tid & 15;   // 0..15

    float acc[8][8];
#pragma unroll
    for (int i = 0; i < 8; i++)
#pragma unroll
        for (int j = 0; j < 8; j++) acc[i][j] = 0.f;

    for (int k0 = 0; k0 < K; k0 += 8) {
        float4 av = *(const float4*)(A + (size_t)(bm + arow) * K + k0 + acol);
        As[acol + 0][arow] = av.x;
        As[acol + 1][arow] = av.y;
        As[acol + 2][arow] = av.z;
        As[acol + 3][arow] = av.w;
        *(float4*)(&Bs[brow][bcol]) =
            *(const float4*)(W + (size_t)(k0 + brow) * N + bn + bcol);
        __syncthreads();

#pragma unroll
        for (int kk = 0; kk < 8; kk++) {
            float a[8], b[8];
            *(float4*)&a[0] = *(float4*)&As[kk][tr * 4];
            *(float4*)&a[4] = *(float4*)&As[kk][tr * 4 + 64];
            *(float4*)&b[0] = *(float4*)&Bs[kk][tc * 4];
            *(float4*)&b[4] = *(float4*)&Bs[kk][tc * 4 + 64];
#pragma unroll
            for (int i = 0; i < 8; i++)
#pragma unroll
                for (int j = 0; j < 8; j++)
                    acc[i][j] += a[i] * b[j];
        }
        __syncthreads();
    }

    // Epilogue
#pragma unroll
    for (int ih = 0; ih < 2; ih++)
#pragma unroll
    for (int i = 0; i < 4; i++) {
        const int r = bm + ih * 64 + tr * 4 + i;
#pragma unroll
        for (int jh = 0; jh < 2; jh++) {
            const int c = bn + jh * 64 + tc * 4;
            float4 v;
            v.x = acc[ih * 4 + i][jh * 4 + 0] * scale;
            v.y = acc[ih * 4 + i][jh * 4 + 1] * scale;
            v.z = acc[ih * 4 + i][jh * 4 + 2] * scale;
            v.w = acc[ih * 4 + i][jh * 4 + 3] * scale;
            if (mode == 0) {
                *(float4*)(C + (size_t)r * N + c) = v;
            } else {
                const int bb = r / L_;
                const int l  = r - bb * L_;
                const int h  = c >> 6;       // D_=64
                const int d  = c & 63;
                const size_t idx = (((size_t)(bb * NH_ + h)) * L_ + l) * D_ + d;
                *(float4*)(C + idx) = v;
            }
        }
    }
}

// ---------------------------------------------------------------------------
// Flash attention: per block = one (batch-head, 64-query tile)
// Q pre-scaled. S = Q K^T + bias; online softmax; O += P V.
// 256 threads: ty=tid/16 rows (4 each), tx=tid%16 cols (4 each).
// Smem: Qs[64][65], Ks[64][65] (reused as P), Vs[64][64]  -> 49664 bytes dyn.
// ---------------------------------------------------------------------------
#define QS_STRIDE 65
#define ATTN_SMEM ((64 * 65 * 2 + 64 * 64) * 4)

__global__ __launch_bounds__(256) void attn_kernel(
    const float* __restrict__ Q, const float* __restrict__ K,
    const float* __restrict__ V, const float* __restrict__ bias,
    float* __restrict__ Out)
{
    extern __shared__ float sm[];
    float* Qs = sm;                     // 64 x 65
    float* Ks = Qs + 64 * QS_STRIDE;    // 64 x 65 (later holds P)
    float* Vs = Ks + 64 * QS_STRIDE;    // 64 x 64

    const int tid = threadIdx.x;
    const int bh  = blockIdx.y;
    const int q0  = blockIdx.x * 64;
    const int bb  = bh / NH_;
    const int h   = bh - bb * NH_;

    const float* Qb = Q + (size_t)bh * L_ * D_;
    const float* Kb = K + (size_t)bh * L_ * D_;
    const float* Vb = V + (size_t)bh * L_ * D_;

    // Load Q tile
    for (int i = tid; i < 64 * 16; i += 256) {
        const int r = i >> 4;
        const int c = (i & 15) << 2;
        float4 v = *(const float4*)(Qb + (size_t)(q0 + r) * D_ + c);
        Qs[r * QS_STRIDE + c + 0] = v.x;
        Qs[r * QS_STRIDE + c + 1] = v.y;
        Qs[r * QS_STRIDE + c + 2] = v.z;
        Qs[r * QS_STRIDE + c + 3] = v.w;
    }

    const int ty = tid >> 4, tx = tid & 15;
    const int r0 = ty * 4, c0 = tx * 4;

    float o[4][4];
    float mrow[4], lrow[4];
#pragma unroll
    for (int i = 0; i < 4; i++) {
        mrow[i] = -1e30f;
        lrow[i] = 0.f;
#pragma unroll
        for (int j = 0; j < 4; j++) o[i][j] = 0.f;
    }
    __syncthreads();

    for (int kv0 = 0; kv0 < L_; kv0 += 64) {
        // Load K (padded, scalar) and V (natural, float4) tiles
        for (int i = tid; i < 64 * 16; i += 256) {
            const int r = i >> 4;
            const int c = (i & 15) << 2;
            float4 kv = *(const float4*)(Kb + (size_t)(kv0 + r) * D_ + c);
            Ks[r * QS_STRIDE + c + 0] = kv.x;
            Ks[r * QS_STRIDE + c + 1] = kv.y;
            Ks[r * QS_STRIDE + c + 2] = kv.z;
            Ks[r * QS_STRIDE + c + 3] = kv.w;
            *(float4*)(Vs + r * 64 + c) =
                *(const float4*)(Vb + (size_t)(kv0 + r) * D_ + c);
        }
        __syncthreads();

        // S = Q K^T  (contraction over d)
        float s[4][4];
#pragma unroll
        for (int i = 0; i < 4; i++)
#pragma unroll
            for (int j = 0; j < 4; j++) s[i][j] = 0.f;

#pragma unroll 16
        for (int kk = 0; kk < 64; kk++) {
            float a[4], bbv[4];
#pragma unroll
            for (int i = 0; i < 4; i++) a[i]   = Qs[(r0 + i) * QS_STRIDE + kk];
#pragma unroll
            for (int j = 0; j < 4; j++) bbv[j] = Ks[(c0 + j) * QS_STRIDE + kk];
#pragma unroll
            for (int i = 0; i < 4; i++)
#pragma unroll
                for (int j = 0; j < 4; j++)
                    s[i][j] += a[i] * bbv[j];
        }

        // + bias
#pragma unroll
        for (int i = 0; i < 4; i++) {
            float4 bv = *(const float4*)(bias + (size_t)(q0 + r0 + i) * L_ + kv0 + c0);
            s[i][0] += bv.x; s[i][1] += bv.y; s[i][2] += bv.z; s[i][3] += bv.w;
        }

        // Online softmax update (reduce across the 16 lanes of each row group)
#pragma unroll
        for (int i = 0; i < 4; i++) {
            float mx = fmaxf(fmaxf(s[i][0], s[i][1]), fmaxf(s[i][2], s[i][3]));
#pragma unroll
            for (int off = 8; off > 0; off >>= 1)
                mx = fmaxf(mx, __shfl_xor_sync(0xffffffffu, mx, off));
            const float mnew  = fmaxf(mrow[i], mx);
            const float alpha = __expf(mrow[i] - mnew);
            float psum = 0.f;
#pragma unroll
            for (int j = 0; j < 4; j++) {
                s[i][j] = __expf(s[i][j] - mnew);
                psum += s[i][j];
            }
#pragma unroll
            for (int off = 8; off > 0; off >>= 1)
                psum += __shfl_xor_sync(0xffffffffu, psum, off);
            lrow[i] = lrow[i] * alpha + psum;
            mrow[i] = mnew;
#pragma unroll
            for (int j = 0; j < 4; j++) o[i][j] *= alpha;
        }
        __syncthreads();   // all reads of Ks done before overwrite with P

        // Store P into Ks buffer
#pragma unroll
        for (int i = 0; i < 4; i++)
#pragma unroll
            for (int j = 0; j < 4; j++)
                Ks[(r0 + i) * QS_STRIDE + c0 + j] = s[i][j];
        __syncthreads();

        // O += P @ V
#pragma unroll 16
        for (int kk = 0; kk < 64; kk++) {
            float a[4];
#pragma unroll
            for (int i = 0; i < 4; i++) a[i] = Ks[(r0 + i) * QS_STRIDE + kk];
            float4 bv = *(float4*)(Vs + kk * 64 + c0);
#pragma unroll
            for (int i = 0; i < 4; i++) {
                o[i][0] += a[i] * bv.x;
                o[i][1] += a[i] * bv.y;
                o[i][2] += a[i] * bv.z;
                o[i][3] += a[i] * bv.w;
            }
        }
        __syncthreads();   // before next tile's K/V loads
    }

    // Write normalized output into [B*L, H] layout
#pragma unroll
    for (int i = 0; i < 4; i++) {
        const float inv = 1.0f / lrow[i];
        float4 v;
        v.x = o[i][0] * inv; v.y = o[i][1] * inv;
        v.z = o[i][2] * inv; v.w = o[i][3] * inv;
        *(float4*)(Out + (size_t)(bb * L_ + q0 + r0 + i) * H_ + h * D_ + c0) = v;
    }
}

// ---------------------------------------------------------------------------
extern "C" void kernel_launch(void* const* d_in, const int* in_sizes, int n_in,
                              void* d_out, int out_size)
{
    (void)in_sizes; (void)n_in; (void)out_size;
    const float* x    = (const float*)d_in[0];
    const float* y    = (const float*)d_in[1];
    const float* bias = (const float*)d_in[2];
    const float* Wq   = (const float*)d_in[3];
    const float* Wk   = (const float*)d_in[4];
    const float* Wv   = (const float*)d_in[5];
    const float* Wo   = (const float*)d_in[6];
    float* out = (float*)d_out;

    float *Qp, *Kp, *Vp, *Tp;
    cudaGetSymbolAddress((void**)&Qp, g_Q);
    cudaGetSymbolAddress((void**)&Kp, g_K);
    cudaGetSymbolAddress((void**)&Vp, g_V);
    cudaGetSymbolAddress((void**)&Tp, g_T);

    cudaFuncSetAttribute(attn_kernel,
                         cudaFuncAttributeMaxDynamicSharedMemorySize, ATTN_SMEM);

    const float qscale = 1.0f / sqrtf((float)D_);   // 0.125

    dim3 gemm_grid(H_ / 128, M_ / 128);   // (8, 32)
    // Q/K/V projections (head-split epilogue)
    sgemm_kernel<<<gemm_grid, 256>>>(x, Wq, Qp, M_, H_, H_, 1, qscale);
    sgemm_kernel<<<gemm_grid, 256>>>(y, Wk, Kp, M_, H_, H_, 1, 1.0f);
    sgemm_kernel<<<gemm_grid, 256>>>(y, Wv, Vp, M_, H_, H_, 1, 1.0f);

    // Attention
    dim3 attn_grid(L_ / 64, BH_);         // (32, 32)
    attn_kernel<<<attn_grid, 256, ATTN_SMEM>>>(Qp, Kp, Vp, bias, Tp);

    // Output projection
    sgemm_kernel<<<gemm_grid, 256>>>(Tp, Wo, out, M_, H_, H_, 0, 1.0f);
}

// round 2
// speedup vs baseline: 1.0018x; 1.0018x over previous
#include <cuda_runtime.h>
#include <math.h>

// Problem constants
#define B_   2
#define L_   2048
#define H_   1024
#define NH_  16
#define D_   64
#define M_   (B_ * L_)      // 4096
#define BH_  (B_ * NH_)     // 32

// Scratch (device globals; no allocation allowed)
__device__ float g_Q[(size_t)BH_ * L_ * D_];   // [B*NH, L, D], pre-scaled by D^-0.5
__device__ float g_K[(size_t)BH_ * L_ * D_];   // [B*NH, L, D]
__device__ float g_V[(size_t)BH_ * L_ * D_];   // [B*NH, L, D]
__device__ float g_T[(size_t)M_ * H_];         // attention output, [B*L, H]

// ---------------------------------------------------------------------------
// SGEMM: C[M,N] = A[M,K] @ W[K,N]  (row-major)
// mode 0: plain row-major store (scaled)
// mode 1: head-split store into [B*NH, L, D] (scaled)
// BM=BN=128, BK=8, 256 threads, 8x8 micro-tile (split 4+4 layout)
// ---------------------------------------------------------------------------
__global__ __launch_bounds__(256) void sgemm_kernel(
    const float* __restrict__ A, const float* __restrict__ W,
    float* __restrict__ C, int M, int K, int N, int mode, float scale)
{
    __shared__ float As[8][128];
    __shared__ float Bs[8][128];

    const int tid  = threadIdx.x;
    const int bm   = blockIdx.y * 128;
    const int bn   = blockIdx.x * 128;
    const int arow = tid >> 1;
    const int acol = (tid & 1) << 2;
    const int brow = tid >> 5;
    const int bcol = (tid & 31) << 2;
    const int tr   = tid >> 4;   // 0..15
    const int tc   = tid & 15;   // 0..15

    float acc[8][8];
#pragma unroll
    for (int i = 0; i < 8; i++)
#pragma unroll
        for (int j = 0; j < 8; j++) acc[i][j] = 0.f;

    for (int k0 = 0; k0 < K; k0 += 8) {
        float4 av = *(const float4*)(A + (size_t)(bm + arow) * K + k0 + acol);
        As[acol + 0][arow] = av.x;
        As[acol + 1][arow] = av.y;
        As[acol + 2][arow] = av.z;
        As[acol + 3][arow] = av.w;
        *(float4*)(&Bs[brow][bcol]) =
            *(const float4*)(W + (size_t)(k0 + brow) * N + bn + bcol);
        __syncthreads();

#pragma unroll
        for (int kk = 0; kk < 8; kk++) {
            float a[8], b[8];
            *(float4*)&a[0] = *(float4*)&As[kk][tr * 4];
            *(float4*)&a[4] = *(float4*)&As[kk][tr * 4 + 64];
            *(float4*)&b[0] = *(float4*)&Bs[kk][tc * 4];
            *(float4*)&b[4] = *(float4*)&Bs[kk][tc * 4 + 64];
#pragma unroll
            for (int i = 0; i < 8; i++)
#pragma unroll
                for (int j = 0; j < 8; j++)
                    acc[i][j] += a[i] * b[j];
        }
        __syncthreads();
    }

    // Epilogue
#pragma unroll
    for (int ih = 0; ih < 2; ih++)
#pragma unroll
    for (int i = 0; i < 4; i++) {
        const int r = bm + ih * 64 + tr * 4 + i;
#pragma unroll
        for (int jh = 0; jh < 2; jh++) {
            const int c = bn + jh * 64 + tc * 4;
            float4 v;
            v.x = acc[ih * 4 + i][jh * 4 + 0] * scale;
            v.y = acc[ih * 4 + i][jh * 4 + 1] * scale;
            v.z = acc[ih * 4 + i][jh * 4 + 2] * scale;
            v.w = acc[ih * 4 + i][jh * 4 + 3] * scale;
            if (mode == 0) {
                *(float4*)(C + (size_t)r * N + c) = v;
            } else {
                const int bb = r / L_;
                const int l  = r - bb * L_;
                const int h  = c >> 6;       // D_=64
                const int d  = c & 63;
                const size_t idx = (((size_t)(bb * NH_ + h)) * L_ + l) * D_ + d;
                *(float4*)(C + idx) = v;
            }
        }
    }
}

// ---------------------------------------------------------------------------
// Flash attention: per block = one (batch-head, 64-query tile)
// Q pre-scaled. S = Q K^T + bias; online softmax; O += P V.
// 256 threads: ty=tid/16 rows (4 each), tx=tid%16 cols (4 each).
// Smem: Qs[64][65], Ks[64][65] (reused as P), Vs[64][64]  -> 49664 bytes dyn.
// ---------------------------------------------------------------------------
#define QS_STRIDE 65
#define ATTN_SMEM ((64 * 65 * 2 + 64 * 64) * 4)

__global__ __launch_bounds__(256) void attn_kernel(
    const float* __restrict__ Q, const float* __restrict__ K,
    const float* __restrict__ V, const float* __restrict__ bias,
    float* __restrict__ Out)
{
    extern __shared__ float sm[];
    float* Qs = sm;                     // 64 x 65
    float* Ks = Qs + 64 * QS_STRIDE;    // 64 x 65 (later holds P)
    float* Vs = Ks + 64 * QS_STRIDE;    // 64 x 64

    const int tid = threadIdx.x;
    const int bh  = blockIdx.y;
    const int q0  = blockIdx.x * 64;
    const int bb  = bh / NH_;
    const int h   = bh - bb * NH_;

    const float* Qb = Q + (size_t)bh * L_ * D_;
    const float* Kb = K + (size_t)bh * L_ * D_;
    const float* Vb = V + (size_t)bh * L_ * D_;

    // Load Q tile
    for (int i = tid; i < 64 * 16; i += 256) {
        const int r = i >> 4;
        const int c = (i & 15) << 2;
        float4 v = *(const float4*)(Qb + (size_t)(q0 + r) * D_ + c);
        Qs[r * QS_STRIDE + c + 0] = v.x;
        Qs[r * QS_STRIDE + c + 1] = v.y;
        Qs[r * QS_STRIDE + c + 2] = v.z;
        Qs[r * QS_STRIDE + c + 3] = v.w;
    }

    const int ty = tid >> 4, tx = tid & 15;
    const int r0 = ty * 4, c0 = tx * 4;

    float o[4][4];
    float mrow[4], lrow[4];
#pragma unroll
    for (int i = 0; i < 4; i++) {
        mrow[i] = -1e30f;
        lrow[i] = 0.f;
#pragma unroll
        for (int j = 0; j < 4; j++) o[i][j] = 0.f;
    }
    __syncthreads();

    for (int kv0 = 0; kv0 < L_; kv0 += 64) {
        // Load K (padded, scalar) and V (natural, float4) tiles
        for (int i = tid; i < 64 * 16; i += 256) {
            const int r = i >> 4;
            const int c = (i & 15) << 2;
            float4 kv = *(const float4*)(Kb + (size_t)(kv0 + r) * D_ + c);
            Ks[r * QS_STRIDE + c + 0] = kv.x;
            Ks[r * QS_STRIDE + c + 1] = kv.y;
            Ks[r * QS_STRIDE + c + 2] = kv.z;
            Ks[r * QS_STRIDE + c + 3] = kv.w;
            *(float4*)(Vs + r * 64 + c) =
                *(const float4*)(Vb + (size_t)(kv0 + r) * D_ + c);
        }
        __syncthreads();

        // S = Q K^T  (contraction over d)
        float s[4][4];
#pragma unroll
        for (int i = 0; i < 4; i++)
#pragma unroll
            for (int j = 0; j < 4; j++) s[i][j] = 0.f;

#pragma unroll 16
        for (int kk = 0; kk < 64; kk++) {
            float a[4], bbv[4];
#pragma unroll
            for (int i = 0; i < 4; i++) a[i]   = Qs[(r0 + i) * QS_STRIDE + kk];
#pragma unroll
            for (int j = 0; j < 4; j++) bbv[j] = Ks[(c0 + j) * QS_STRIDE + kk];
#pragma unroll
            for (int i = 0; i < 4; i++)
#pragma unroll
                for (int j = 0; j < 4; j++)
                    s[i][j] += a[i] * bbv[j];
        }

        // + bias
#pragma unroll
        for (int i = 0; i < 4; i++) {
            float4 bv = *(const float4*)(bias + (size_t)(q0 + r0 + i) * L_ + kv0 + c0);
            s[i][0] += bv.x; s[i][1] += bv.y; s[i][2] += bv.z; s[i][3] += bv.w;
        }

        // Online softmax update (reduce across the 16 lanes of each row group)
#pragma unroll
        for (int i = 0; i < 4; i++) {
            float mx = fmaxf(fmaxf(s[i][0], s[i][1]), fmaxf(s[i][2], s[i][3]));
#pragma unroll
            for (int off = 8; off > 0; off >>= 1)
                mx = fmaxf(mx, __shfl_xor_sync(0xffffffffu, mx, off));
            const float mnew  = fmaxf(mrow[i], mx);
            const float alpha = __expf(mrow[i] - mnew);
            float psum = 0.f;
#pragma unroll
            for (int j = 0; j < 4; j++) {
                s[i][j] = __expf(s[i][j] - mnew);
                psum += s[i][j];
            }
#pragma unroll
            for (int off = 8; off > 0; off >>= 1)
                psum += __shfl_xor_sync(0xffffffffu, psum, off);
            lrow[i] = lrow[i] * alpha + psum;
            mrow[i] = mnew;
#pragma unroll
            for (int j = 0; j < 4; j++) o[i][j] *= alpha;
        }
        __syncthreads();   // all reads of Ks done before overwrite with P

        // Store P into Ks buffer
#pragma unroll
        for (int i = 0; i < 4; i++)
#pragma unroll
            for (int j = 0; j < 4; j++)
                Ks[(r0 + i) * QS_STRIDE + c0 + j] = s[i][j];
        __syncthreads();

        // O += P @ V
#pragma unroll 16
        for (int kk = 0; kk < 64; kk++) {
            float a[4];
#pragma unroll
            for (int i = 0; i < 4; i++) a[i] = Ks[(r0 + i) * QS_STRIDE + kk];
            float4 bv = *(float4*)(Vs + kk * 64 + c0);
#pragma unroll
            for (int i = 0; i < 4; i++) {
                o[i][0] += a[i] * bv.x;
                o[i][1] += a[i] * bv.y;
                o[i][2] += a[i] * bv.z;
                o[i][3] += a[i] * bv.w;
            }
        }
        __syncthreads();   // before next tile's K/V loads
    }

    // Write normalized output into [B*L, H] layout
#pragma unroll
    for (int i = 0; i < 4; i++) {
        const float inv = 1.0f / lrow[i];
        float4 v;
        v.x = o[i][0] * inv; v.y = o[i][1] * inv;
        v.z = o[i][2] * inv; v.w = o[i][3] * inv;
        *(float4*)(Out + (size_t)(bb * L_ + q0 + r0 + i) * H_ + h * D_ + c0) = v;
    }
}

// ---------------------------------------------------------------------------
extern "C" void kernel_launch(void* const* d_in, const int* in_sizes, int n_in,
                              void* d_out, int out_size)
{
    (void)in_sizes; (void)n_in; (void)out_size;
    const float* x    = (const float*)d_in[0];
    const float* y    = (const float*)d_in[1];
    const float* bias = (const float*)d_in[2];
    const float* Wq   = (const float*)d_in[3];
    const float* Wk   = (const float*)d_in[4];
    const float* Wv   = (const float*)d_in[5];
    const float* Wo   = (const float*)d_in[6];
    float* out = (float*)d_out;

    float *Qp, *Kp, *Vp, *Tp;
    cudaGetSymbolAddress((void**)&Qp, g_Q);
    cudaGetSymbolAddress((void**)&Kp, g_K);
    cudaGetSymbolAddress((void**)&Vp, g_V);
    cudaGetSymbolAddress((void**)&Tp, g_T);

    cudaFuncSetAttribute(attn_kernel,
                         cudaFuncAttributeMaxDynamicSharedMemorySize, ATTN_SMEM);

    const float qscale = 1.0f / sqrtf((float)D_);   // 0.125

    dim3 gemm_grid(H_ / 128, M_ / 128);   // (8, 32)
    // Q/K/V projections (head-split epilogue)
    sgemm_kernel<<<gemm_grid, 256>>>(x, Wq, Qp, M_, H_, H_, 1, qscale);
    sgemm_kernel<<<gemm_grid, 256>>>(y, Wk, Kp, M_, H_, H_, 1, 1.0f);
    sgemm_kernel<<<gemm_grid, 256>>>(y, Wv, Vp, M_, H_, H_, 1, 1.0f);

    // Attention
    dim3 attn_grid(L_ / 64, BH_);         // (32, 32)
    attn_kernel<<<attn_grid, 256, ATTN_SMEM>>>(Qp, Kp, Vp, bias, Tp);

    // Output projection
    sgemm_kernel<<<gemm_grid, 256>>>(Tp, Wo, out, M_, H_, H_, 0, 1.0f);
}

// round 3
// speedup vs baseline: 2.4284x; 2.4240x over previous
#include <cuda_runtime.h>
#include <math.h>
#include <stdint.h>

#define B_   2
#define L_   2048
#define H_   1024
#define NH_  16
#define D_   64
#define M_   (B_ * L_)
#define BH_  (B_ * NH_)

__device__ float g_Q[(size_t)BH_ * L_ * D_];
__device__ float g_K[(size_t)BH_ * L_ * D_];
__device__ float g_V[(size_t)BH_ * L_ * D_];
__device__ float g_T[(size_t)M_ * H_];

__device__ __forceinline__ uint32_t f2tf(float f) {
    uint32_t u;
    asm("cvt.rna.tf32.f32 %0, %1;" : "=r"(u) : "f"(f));
    return u;
}
__device__ __forceinline__ uint4 f2tf4(float4 v) {
    return make_uint4(f2tf(v.x), f2tf(v.y), f2tf(v.z), f2tf(v.w));
}
__device__ __forceinline__ void mma_tf32(float* d,
    uint32_t a0, uint32_t a1, uint32_t a2, uint32_t a3,
    uint32_t b0, uint32_t b1)
{
    asm volatile(
        "mma.sync.aligned.m16n8k8.row.col.f32.tf32.tf32.f32 "
        "{%0,%1,%2,%3}, {%4,%5,%6,%7}, {%8,%9}, {%0,%1,%2,%3};"
        : "+f"(d[0]), "+f"(d[1]), "+f"(d[2]), "+f"(d[3])
        : "r"(a0), "r"(a1), "r"(a2), "r"(a3), "r"(b0), "r"(b1));
}

// ---------------------------------------------------------------------------
// tf32 GEMM: C[M,N] = A[M,K] @ W[K,N].  CTA 128x128, BK=32, 256 thr.
// ---------------------------------------------------------------------------
#define AS_STRIDE 36
#define BS_STRIDE 136

__global__ __launch_bounds__(256) void gemm_tf32(
    const float* __restrict__ A, const float* __restrict__ W,
    float* __restrict__ C, int M, int K, int N, int mode, float scale)
{
    __shared__ uint32_t As[128 * AS_STRIDE];
    __shared__ uint32_t Bs[32 * BS_STRIDE];

    const int tid  = threadIdx.x;
    const int bm   = blockIdx.y * 128;
    const int bn   = blockIdx.x * 128;
    const int lane = tid & 31;
    const int warp = tid >> 5;
    const int g    = lane >> 2;
    const int tg   = lane & 3;
    const int m0b  = (warp >> 1) * 32;
    const int n0b  = (warp & 1) * 64;

    float acc[2][8][4];
#pragma unroll
    for (int mt = 0; mt < 2; mt++)
#pragma unroll
        for (int nt = 0; nt < 8; nt++)
#pragma unroll
            for (int r = 0; r < 4; r++) acc[mt][nt][r] = 0.f;

    for (int k0 = 0; k0 < K; k0 += 32) {
#pragma unroll
        for (int it = 0; it < 4; it++) {
            const int idx = tid + it * 256;
            const int m  = idx >> 3;
            const int kq = (idx & 7) << 2;
            *(uint4*)(As + m * AS_STRIDE + kq) =
                f2tf4(*(const float4*)(A + (size_t)(bm + m) * K + k0 + kq));
            const int kr = idx >> 5;
            const int nq = (idx & 31) << 2;
            *(uint4*)(Bs + kr * BS_STRIDE + nq) =
                f2tf4(*(const float4*)(W + (size_t)(k0 + kr) * N + bn + nq));
        }
        __syncthreads();

#pragma unroll
        for (int ks = 0; ks < 4; ks++) {
            const int kl = ks * 8;
            uint32_t bf[8][2];
#pragma unroll
            for (int nt = 0; nt < 8; nt++) {
                const int n0 = n0b + nt * 8;
                bf[nt][0] = Bs[(kl + tg) * BS_STRIDE + n0 + g];
                bf[nt][1] = Bs[(kl + tg + 4) * BS_STRIDE + n0 + g];
            }
#pragma unroll
            for (int mt = 0; mt < 2; mt++) {
                const int m0 = m0b + mt * 16;
                uint32_t a0 = As[(m0 + g) * AS_STRIDE + kl + tg];
                uint32_t a1 = As[(m0 + g + 8) * AS_STRIDE + kl + tg];
                uint32_t a2 = As[(m0 + g) * AS_STRIDE + kl + tg + 4];
                uint32_t a3 = As[(m0 + g + 8) * AS_STRIDE + kl + tg + 4];
#pragma unroll
                for (int nt = 0; nt < 8; nt++)
                    mma_tf32(acc[mt][nt], a0, a1, a2, a3, bf[nt][0], bf[nt][1]);
            }
        }
        __syncthreads();
    }

#pragma unroll
    for (int mt = 0; mt < 2; mt++) {
        const int r1 = bm + m0b + mt * 16 + g;
#pragma unroll
        for (int nt = 0; nt < 8; nt++) {
            const int c = bn + n0b + nt * 8 + tg * 2;
            float2 v1 = make_float2(acc[mt][nt][0] * scale, acc[mt][nt][1] * scale);
            float2 v2 = make_float2(acc[mt][nt][2] * scale, acc[mt][nt][3] * scale);
            if (mode == 0) {
                *(float2*)(C + (size_t)r1 * N + c)       = v1;
                *(float2*)(C + (size_t)(r1 + 8) * N + c) = v2;
            } else {
                const int hh = c >> 6;
                const int dd = c & 63;
                int bb = r1 / L_, l = r1 - bb * L_;
                *(float2*)(C + (((size_t)(bb * NH_ + hh)) * L_ + l) * D_ + dd) = v1;
                const int r2 = r1 + 8;
                bb = r2 / L_; l = r2 - bb * L_;
                *(float2*)(C + (((size_t)(bb * NH_ + hh)) * L_ + l) * D_ + dd) = v2;
            }
        }
    }
}

// ---------------------------------------------------------------------------
// Flash attention, tf32 mma. CTA: 128 q-rows of one batch-head. 8 warps.
// ---------------------------------------------------------------------------
#define QS_STR 68
#define VS_STR 72
#define PS_STR 132
#define ATTN_SMEM ((128 * QS_STR * 2 + 128 * VS_STR + 128 * PS_STR) * 4)

__global__ __launch_bounds__(256) void attn_tf32(
    const float* __restrict__ Q, const float* __restrict__ K,
    const float* __restrict__ V, const float* __restrict__ bias,
    float* __restrict__ Out)
{
    extern __shared__ uint32_t su[];
    uint32_t* Qs = su;                       // [q][d]
    uint32_t* Ks = Qs + 128 * QS_STR;        // [key][d]
    uint32_t* Vs = Ks + 128 * QS_STR;        // [key][d]
    uint32_t* Ps = Vs + 128 * VS_STR;        // [q][key]

    const int tid  = threadIdx.x;
    const int lane = tid & 31;
    const int w    = tid >> 5;
    const int g    = lane >> 2;
    const int tg   = lane & 3;
    const int bh   = blockIdx.y;
    const int q0   = blockIdx.x * 128;
    const int bb   = bh / NH_;
    const int hh   = bh - bb * NH_;

    const float* Qb = Q + (size_t)bh * L_ * D_;
    const float* Kb = K + (size_t)bh * L_ * D_;
    const float* Vb = V + (size_t)bh * L_ * D_;

#pragma unroll
    for (int it = 0; it < 8; it++) {
        const int idx = tid + it * 256;
        const int r  = idx >> 4;
        const int cq = (idx & 15) << 2;
        *(uint4*)(Qs + r * QS_STR + cq) =
            f2tf4(*(const float4*)(Qb + (size_t)(q0 + r) * D_ + cq));
    }

    const int qrow = w * 16 + g;

    float o[8][4];
#pragma unroll
    for (int n = 0; n < 8; n++)
#pragma unroll
        for (int r = 0; r < 4; r++) o[n][r] = 0.f;
    float mrun0 = -1e30f, mrun1 = -1e30f, lrun0 = 0.f, lrun1 = 0.f;

    for (int kv0 = 0; kv0 < L_; kv0 += 128) {
        __syncthreads();   // previous iter's Ks/Vs reads done
#pragma unroll
        for (int it = 0; it < 8; it++) {
            const int idx = tid + it * 256;
            const int r  = idx >> 4;
            const int cq = (idx & 15) << 2;
            *(uint4*)(Ks + r * QS_STR + cq) =
                f2tf4(*(const float4*)(Kb + (size_t)(kv0 + r) * D_ + cq));
            *(uint4*)(Vs + r * VS_STR + cq) =
                f2tf4(*(const float4*)(Vb + (size_t)(kv0 + r) * D_ + cq));
        }
        __syncthreads();

        // S init from bias
        float s[16][4];
#pragma unroll
        for (int j = 0; j < 16; j++) {
            const float* bp = bias + (size_t)(q0 + qrow) * L_ + kv0 + j * 8 + tg * 2;
            float2 b1 = *(const float2*)bp;
            float2 b2 = *(const float2*)(bp + (size_t)8 * L_);
            s[j][0] = b1.x; s[j][1] = b1.y; s[j][2] = b2.x; s[j][3] = b2.y;
        }

        // S += Q K^T
#pragma unroll
        for (int ks = 0; ks < 8; ks++) {
            const int kl = ks * 8;
            uint32_t a0 = Qs[qrow * QS_STR + kl + tg];
            uint32_t a1 = Qs[(qrow + 8) * QS_STR + kl + tg];
            uint32_t a2 = Qs[qrow * QS_STR + kl + tg + 4];
            uint32_t a3 = Qs[(qrow + 8) * QS_STR + kl + tg + 4];
#pragma unroll
            for (int j = 0; j < 16; j++) {
                uint32_t b0 = Ks[(j * 8 + g) * QS_STR + kl + tg];
                uint32_t b1 = Ks[(j * 8 + g) * QS_STR + kl + tg + 4];
                mma_tf32(s[j], a0, a1, a2, a3, b0, b1);
            }
        }

        // Online softmax (rows qrow, qrow+8; reduce over tg lanes)
        float mx0 = -1e30f, mx1 = -1e30f;
#pragma unroll
        for (int j = 0; j < 16; j++) {
            mx0 = fmaxf(mx0, fmaxf(s[j][0], s[j][1]));
            mx1 = fmaxf(mx1, fmaxf(s[j][2], s[j][3]));
        }
        mx0 = fmaxf(mx0, __shfl_xor_sync(0xffffffffu, mx0, 1));
        mx0 = fmaxf(mx0, __shfl_xor_sync(0xffffffffu, mx0, 2));
        mx1 = fmaxf(mx1, __shfl_xor_sync(0xffffffffu, mx1, 1));
        mx1 = fmaxf(mx1, __shfl_xor_sync(0xffffffffu, mx1, 2));

        const float mn0 = fmaxf(mrun0, mx0);
        const float mn1 = fmaxf(mrun1, mx1);
        const float al0 = __expf(mrun0 - mn0);
        const float al1 = __expf(mrun1 - mn1);
        float sum0 = 0.f, sum1 = 0.f;
#pragma unroll
        for (int j = 0; j < 16; j++) {
            s[j][0] = __expf(s[j][0] - mn0); sum0 += s[j][0];
            s[j][1] = __expf(s[j][1] - mn0); sum0 += s[j][1];
            s[j][2] = __expf(s[j][2] - mn1); sum1 += s[j][2];
            s[j][3] = __expf(s[j][3] - mn1); sum1 += s[j][3];
        }
        sum0 += __shfl_xor_sync(0xffffffffu, sum0, 1);
        sum0 += __shfl_xor_sync(0xffffffffu, sum0, 2);
        sum1 += __shfl_xor_sync(0xffffffffu, sum1, 1);
        sum1 += __shfl_xor_sync(0xffffffffu, sum1, 2);
        lrun0 = lrun0 * al0 + sum0;
        lrun1 = lrun1 * al1 + sum1;
        mrun0 = mn0;
        mrun1 = mn1;
#pragma unroll
        for (int n = 0; n < 8; n++) {
            o[n][0] *= al0; o[n][1] *= al0;
            o[n][2] *= al1; o[n][3] *= al1;
        }

        // P -> smem (tf32); rows are warp-private
#pragma unroll
        for (int j = 0; j < 16; j++) {
            const int col = j * 8 + tg * 2;
            *(uint2*)(Ps + qrow * PS_STR + col) =
                make_uint2(f2tf(s[j][0]), f2tf(s[j][1]));
            *(uint2*)(Ps + (qrow + 8) * PS_STR + col) =
                make_uint2(f2tf(s[j][2]), f2tf(s[j][3]));
        }
        __syncwarp();

        // O += P V
#pragma unroll
        for (int kk = 0; kk < 16; kk++) {
            const int kl = kk * 8;
            uint32_t a0 = Ps[qrow * PS_STR + kl + tg];
            uint32_t a1 = Ps[(qrow + 8) * PS_STR + kl + tg];
            uint32_t a2 = Ps[qrow * PS_STR + kl + tg + 4];
            uint32_t a3 = Ps[(qrow + 8) * PS_STR + kl + tg + 4];
#pragma unroll
            for (int nt = 0; nt < 8; nt++) {
                uint32_t b0 = Vs[(kl + tg) * VS_STR + nt * 8 + g];
                uint32_t b1 = Vs[(kl + tg + 4) * VS_STR + nt * 8 + g];
                mma_tf32(o[nt], a0, a1, a2, a3, b0, b1);
            }
        }
    }

    // Write normalized output, [B*L, H] layout
    const float inv0 = 1.0f / lrun0;
    const float inv1 = 1.0f / lrun1;
    float* Or0 = Out + (size_t)(bb * L_ + q0 + qrow) * H_ + hh * D_;
    float* Or1 = Or0 + (size_t)8 * H_;
#pragma unroll
    for (int nt = 0; nt < 8; nt++) {
        const int c = nt * 8 + tg * 2;
        *(float2*)(Or0 + c) = make_float2(o[nt][0] * inv0, o[nt][1] * inv0);
        *(float2*)(Or1 + c) = make_float2(o[nt][2] * inv1, o[nt][3] * inv1);
    }
}

// ---------------------------------------------------------------------------
extern "C" void kernel_launch(void* const* d_in, const int* in_sizes, int n_in,
                              void* d_out, int out_size)
{
    (void)in_sizes; (void)n_in; (void)out_size;
    const float* x    = (const float*)d_in[0];
    const float* y    = (const float*)d_in[1];
    const float* bias = (const float*)d_in[2];
    const float* Wq   = (const float*)d_in[3];
    const float* Wk   = (const float*)d_in[4];
    const float* Wv   = (const float*)d_in[5];
    const float* Wo   = (const float*)d_in[6];
    float* out = (float*)d_out;

    float *Qp, *Kp, *Vp, *Tp;
    cudaGetSymbolAddress((void**)&Qp, g_Q);
    cudaGetSymbolAddress((void**)&Kp, g_K);
    cudaGetSymbolAddress((void**)&Vp, g_V);
    cudaGetSymbolAddress((void**)&Tp, g_T);

    cudaFuncSetAttribute(attn_tf32,
                         cudaFuncAttributeMaxDynamicSharedMemorySize, ATTN_SMEM);

    const float qscale = 1.0f / sqrtf((float)D_);

    dim3 gemm_grid(H_ / 128, M_ / 128);
    gemm_tf32<<<gemm_grid, 256>>>(x, Wq, Qp, M_, H_, H_, 1, qscale);
    gemm_tf32<<<gemm_grid, 256>>>(y, Wk, Kp, M_, H_, H_, 1, 1.0f);
    gemm_tf32<<<gemm_grid, 256>>>(y, Wv, Vp, M_, H_, H_, 1, 1.0f);

    dim3 attn_grid(L_ / 128, BH_);
    attn_tf32<<<attn_grid, 256, ATTN_SMEM>>>(Qp, Kp, Vp, bias, Tp);

    gemm_tf32<<<gemm_grid, 256>>>(Tp, Wo, out, M_, H_, H_, 0, 1.0f);
}

// round 4
// speedup vs baseline: 2.8219x; 1.1620x over previous
#include <cuda_runtime.h>
#include <math.h>
#include <stdint.h>

#define B_   2
#define L_   2048
#define H_   1024
#define NH_  16
#define D_   64
#define M_   (B_ * L_)
#define BH_  (B_ * NH_)

__device__ float g_Q[(size_t)BH_ * L_ * D_];
__device__ float g_K[(size_t)BH_ * L_ * D_];
__device__ float g_V[(size_t)BH_ * L_ * D_];
__device__ float g_T[(size_t)M_ * H_];

__device__ __forceinline__ uint32_t f2tf(float f) {
    uint32_t u;
    asm("cvt.rna.tf32.f32 %0, %1;" : "=r"(u) : "f"(f));
    return u;
}
__device__ __forceinline__ uint4 f2tf4(float4 v) {
    return make_uint4(f2tf(v.x), f2tf(v.y), f2tf(v.z), f2tf(v.w));
}
__device__ __forceinline__ void mma_tf32(float* d,
    uint32_t a0, uint32_t a1, uint32_t a2, uint32_t a3,
    uint32_t b0, uint32_t b1)
{
    asm volatile(
        "mma.sync.aligned.m16n8k8.row.col.f32.tf32.tf32.f32 "
        "{%0,%1,%2,%3}, {%4,%5,%6,%7}, {%8,%9}, {%0,%1,%2,%3};"
        : "+f"(d[0]), "+f"(d[1]), "+f"(d[2]), "+f"(d[3])
        : "r"(a0), "r"(a1), "r"(a2), "r"(a3), "r"(b0), "r"(b1));
}

// ---------------------------------------------------------------------------
// tf32 GEMM core: CTA 128x128, BK=32, 256 thr, warp 32x64.
// ---------------------------------------------------------------------------
#define AS_STRIDE 36
#define BS_STRIDE 136

__device__ __forceinline__ void gemm_body(
    const float* __restrict__ A, const float* __restrict__ W,
    float* __restrict__ C, int K, int N, int mode, float scale,
    int bm, int bn, uint32_t* As, uint32_t* Bs)
{
    const int tid  = threadIdx.x;
    const int lane = tid & 31;
    const int warp = tid >> 5;
    const int g    = lane >> 2;
    const int tg   = lane & 3;
    const int m0b  = (warp >> 1) * 32;
    const int n0b  = (warp & 1) * 64;

    float acc[2][8][4];
#pragma unroll
    for (int mt = 0; mt < 2; mt++)
#pragma unroll
        for (int nt = 0; nt < 8; nt++)
#pragma unroll
            for (int r = 0; r < 4; r++) acc[mt][nt][r] = 0.f;

    for (int k0 = 0; k0 < K; k0 += 32) {
#pragma unroll
        for (int it = 0; it < 4; it++) {
            const int idx = tid + it * 256;
            const int m  = idx >> 3;
            const int kq = (idx & 7) << 2;
            *(uint4*)(As + m * AS_STRIDE + kq) =
                f2tf4(*(const float4*)(A + (size_t)(bm + m) * K + k0 + kq));
            const int kr = idx >> 5;
            const int nq = (idx & 31) << 2;
            *(uint4*)(Bs + kr * BS_STRIDE + nq) =
                f2tf4(*(const float4*)(W + (size_t)(k0 + kr) * N + bn + nq));
        }
        __syncthreads();

#pragma unroll
        for (int ks = 0; ks < 4; ks++) {
            const int kl = ks * 8;
            uint32_t bf[8][2];
#pragma unroll
            for (int nt = 0; nt < 8; nt++) {
                const int n0 = n0b + nt * 8;
                bf[nt][0] = Bs[(kl + tg) * BS_STRIDE + n0 + g];
                bf[nt][1] = Bs[(kl + tg + 4) * BS_STRIDE + n0 + g];
            }
#pragma unroll
            for (int mt = 0; mt < 2; mt++) {
                const int m0 = m0b + mt * 16;
                uint32_t a0 = As[(m0 + g) * AS_STRIDE + kl + tg];
                uint32_t a1 = As[(m0 + g + 8) * AS_STRIDE + kl + tg];
                uint32_t a2 = As[(m0 + g) * AS_STRIDE + kl + tg + 4];
                uint32_t a3 = As[(m0 + g + 8) * AS_STRIDE + kl + tg + 4];
#pragma unroll
                for (int nt = 0; nt < 8; nt++)
                    mma_tf32(acc[mt][nt], a0, a1, a2, a3, bf[nt][0], bf[nt][1]);
            }
        }
        __syncthreads();
    }

#pragma unroll
    for (int mt = 0; mt < 2; mt++) {
        const int r1 = bm + m0b + mt * 16 + g;
#pragma unroll
        for (int nt = 0; nt < 8; nt++) {
            const int c = bn + n0b + nt * 8 + tg * 2;
            float2 v1 = make_float2(acc[mt][nt][0] * scale, acc[mt][nt][1] * scale);
            float2 v2 = make_float2(acc[mt][nt][2] * scale, acc[mt][nt][3] * scale);
            if (mode == 0) {
                *(float2*)(C + (size_t)r1 * N + c)       = v1;
                *(float2*)(C + (size_t)(r1 + 8) * N + c) = v2;
            } else {
                const int hh = c >> 6;
                const int dd = c & 63;
                int bb = r1 / L_, l = r1 - bb * L_;
                *(float2*)(C + (((size_t)(bb * NH_ + hh)) * L_ + l) * D_ + dd) = v1;
                const int r2 = r1 + 8;
                bb = r2 / L_; l = r2 - bb * L_;
                *(float2*)(C + (((size_t)(bb * NH_ + hh)) * L_ + l) * D_ + dd) = v2;
            }
        }
    }
}

// Fused Q/K/V projections: blockIdx.z selects (input, weight, dst, scale).
__global__ __launch_bounds__(256, 2) void qkv_gemm(
    const float* __restrict__ x, const float* __restrict__ y,
    const float* __restrict__ Wq, const float* __restrict__ Wk,
    const float* __restrict__ Wv,
    float* __restrict__ Qd, float* __restrict__ Kd, float* __restrict__ Vd,
    float qscale)
{
    __shared__ uint32_t As[128 * AS_STRIDE];
    __shared__ uint32_t Bs[32 * BS_STRIDE];
    const int z = blockIdx.z;
    const float* A = (z == 0) ? x : y;
    const float* W = (z == 0) ? Wq : (z == 1) ? Wk : Wv;
    float* C = (z == 0) ? Qd : (z == 1) ? Kd : Vd;
    const float scale = (z == 0) ? qscale : 1.0f;
    gemm_body(A, W, C, H_, H_, 1, scale, blockIdx.y * 128, blockIdx.x * 128, As, Bs);
}

__global__ __launch_bounds__(256, 2) void out_gemm(
    const float* __restrict__ A, const float* __restrict__ W,
    float* __restrict__ C)
{
    __shared__ uint32_t As[128 * AS_STRIDE];
    __shared__ uint32_t Bs[32 * BS_STRIDE];
    gemm_body(A, W, C, H_, H_, 0, 1.0f, blockIdx.y * 128, blockIdx.x * 128, As, Bs);
}

// ---------------------------------------------------------------------------
// Flash attention, tf32 mma, P kept in registers via quad shuffles.
// CTA: 128 q-rows of one batch-head. 8 warps. 2 CTAs/SM.
// Smem: Qs[128][68] + Ks[128][68] + Vs[128][72] = 106496 B.
// ---------------------------------------------------------------------------
#define QS_STR 68
#define VS_STR 72
#define ATTN_SMEM ((128 * QS_STR * 2 + 128 * VS_STR) * 4)

__global__ __launch_bounds__(256, 2) void attn_tf32(
    const float* __restrict__ Q, const float* __restrict__ K,
    const float* __restrict__ V, const float* __restrict__ bias,
    float* __restrict__ Out)
{
    extern __shared__ uint32_t su[];
    uint32_t* Qs = su;                       // [q][d]
    uint32_t* Ks = Qs + 128 * QS_STR;        // [key][d]
    uint32_t* Vs = Ks + 128 * QS_STR;        // [key][d]

    const int tid  = threadIdx.x;
    const int lane = tid & 31;
    const int w    = tid >> 5;
    const int g    = lane >> 2;
    const int tg   = lane & 3;
    const int bh   = blockIdx.y;
    const int q0   = blockIdx.x * 128;
    const int bb   = bh / NH_;
    const int hh   = bh - bb * NH_;

    const float* Qb = Q + (size_t)bh * L_ * D_;
    const float* Kb = K + (size_t)bh * L_ * D_;
    const float* Vb = V + (size_t)bh * L_ * D_;

#pragma unroll
    for (int it = 0; it < 8; it++) {
        const int idx = tid + it * 256;
        const int r  = idx >> 4;
        const int cq = (idx & 15) << 2;
        *(uint4*)(Qs + r * QS_STR + cq) =
            f2tf4(*(const float4*)(Qb + (size_t)(q0 + r) * D_ + cq));
    }

    const int qrow = w * 16 + g;
    const int srcA = (lane & 28) | (tg >> 1);   // quad base + tg/2
    const bool oddtg = (tg & 1);

    float o[8][4];
#pragma unroll
    for (int n = 0; n < 8; n++)
#pragma unroll
        for (int r = 0; r < 4; r++) o[n][r] = 0.f;
    float mrun0 = -1e30f, mrun1 = -1e30f, lrun0 = 0.f, lrun1 = 0.f;

    for (int kv0 = 0; kv0 < L_; kv0 += 128) {
        __syncthreads();   // previous iter's Ks/Vs reads complete
#pragma unroll
        for (int it = 0; it < 8; it++) {
            const int idx = tid + it * 256;
            const int r  = idx >> 4;
            const int cq = (idx & 15) << 2;
            *(uint4*)(Ks + r * QS_STR + cq) =
                f2tf4(*(const float4*)(Kb + (size_t)(kv0 + r) * D_ + cq));
            *(uint4*)(Vs + r * VS_STR + cq) =
                f2tf4(*(const float4*)(Vb + (size_t)(kv0 + r) * D_ + cq));
        }
        __syncthreads();

        // S init from bias
        float s[16][4];
#pragma unroll
        for (int j = 0; j < 16; j++) {
            const float* bp = bias + (size_t)(q0 + qrow) * L_ + kv0 + j * 8 + tg * 2;
            float2 b1 = *(const float2*)bp;
            float2 b2 = *(const float2*)(bp + (size_t)8 * L_);
            s[j][0] = b1.x; s[j][1] = b1.y; s[j][2] = b2.x; s[j][3] = b2.y;
        }

        // S += Q K^T
#pragma unroll
        for (int ks = 0; ks < 8; ks++) {
            const int kl = ks * 8;
            uint32_t a0 = Qs[qrow * QS_STR + kl + tg];
            uint32_t a1 = Qs[(qrow + 8) * QS_STR + kl + tg];
            uint32_t a2 = Qs[qrow * QS_STR + kl + tg + 4];
            uint32_t a3 = Qs[(qrow + 8) * QS_STR + kl + tg + 4];
#pragma unroll
            for (int j = 0; j < 16; j++) {
                uint32_t b0 = Ks[(j * 8 + g) * QS_STR + kl + tg];
                uint32_t b1 = Ks[(j * 8 + g) * QS_STR + kl + tg + 4];
                mma_tf32(s[j], a0, a1, a2, a3, b0, b1);
            }
        }

        // Online softmax (rows qrow, qrow+8; reduce over tg lanes)
        float mx0 = -1e30f, mx1 = -1e30f;
#pragma unroll
        for (int j = 0; j < 16; j++) {
            mx0 = fmaxf(mx0, fmaxf(s[j][0], s[j][1]));
            mx1 = fmaxf(mx1, fmaxf(s[j][2], s[j][3]));
        }
        mx0 = fmaxf(mx0, __shfl_xor_sync(0xffffffffu, mx0, 1));
        mx0 = fmaxf(mx0, __shfl_xor_sync(0xffffffffu, mx0, 2));
        mx1 = fmaxf(mx1, __shfl_xor_sync(0xffffffffu, mx1, 1));
        mx1 = fmaxf(mx1, __shfl_xor_sync(0xffffffffu, mx1, 2));

        const float mn0 = fmaxf(mrun0, mx0);
        const float mn1 = fmaxf(mrun1, mx1);
        const float al0 = __expf(mrun0 - mn0);
        const float al1 = __expf(mrun1 - mn1);
        float sum0 = 0.f, sum1 = 0.f;
#pragma unroll
        for (int j = 0; j < 16; j++) {
            s[j][0] = __expf(s[j][0] - mn0); sum0 += s[j][0];
            s[j][1] = __expf(s[j][1] - mn0); sum0 += s[j][1];
            s[j][2] = __expf(s[j][2] - mn1); sum1 += s[j][2];
            s[j][3] = __expf(s[j][3] - mn1); sum1 += s[j][3];
        }
        sum0 += __shfl_xor_sync(0xffffffffu, sum0, 1);
        sum0 += __shfl_xor_sync(0xffffffffu, sum0, 2);
        sum1 += __shfl_xor_sync(0xffffffffu, sum1, 1);
        sum1 += __shfl_xor_sync(0xffffffffu, sum1, 2);
        lrun0 = lrun0 * al0 + sum0;
        lrun1 = lrun1 * al1 + sum1;
        mrun0 = mn0;
        mrun1 = mn1;
#pragma unroll
        for (int n = 0; n < 8; n++) {
            o[n][0] *= al0; o[n][1] *= al0;
            o[n][2] *= al1; o[n][3] *= al1;
        }

        // O += P V : build P A-fragments from C-fragments via quad shuffles.
        // C-frag lane(4g+tg) holds cols {2tg, 2tg+1}; A-frag needs cols
        // {tg, tg+4}. col c lives in lane 4g + (c>>1), slot (c&1).
#pragma unroll
        for (int kk = 0; kk < 16; kk++) {
            uint32_t p0 = f2tf(s[kk][0]);
            uint32_t p1 = f2tf(s[kk][1]);
            uint32_t p2 = f2tf(s[kk][2]);
            uint32_t p3 = f2tf(s[kk][3]);
            uint32_t t0, t1;
            t0 = __shfl_sync(0xffffffffu, p0, srcA);
            t1 = __shfl_sync(0xffffffffu, p1, srcA);
            const uint32_t a0 = oddtg ? t1 : t0;
            t0 = __shfl_sync(0xffffffffu, p2, srcA);
            t1 = __shfl_sync(0xffffffffu, p3, srcA);
            const uint32_t a1 = oddtg ? t1 : t0;
            t0 = __shfl_sync(0xffffffffu, p0, srcA + 2);
            t1 = __shfl_sync(0xffffffffu, p1, srcA + 2);
            const uint32_t a2 = oddtg ? t1 : t0;
            t0 = __shfl_sync(0xffffffffu, p2, srcA + 2);
            t1 = __shfl_sync(0xffffffffu, p3, srcA + 2);
            const uint32_t a3 = oddtg ? t1 : t0;

            const int kl = kk * 8;
#pragma unroll
            for (int nt = 0; nt < 8; nt++) {
                uint32_t b0 = Vs[(kl + tg) * VS_STR + nt * 8 + g];
                uint32_t b1 = Vs[(kl + tg + 4) * VS_STR + nt * 8 + g];
                mma_tf32(o[nt], a0, a1, a2, a3, b0, b1);
            }
        }
    }

    // Write normalized output, [B*L, H] layout
    const float inv0 = 1.0f / lrun0;
    const float inv1 = 1.0f / lrun1;
    float* Or0 = Out + (size_t)(bb * L_ + q0 + qrow) * H_ + hh * D_;
    float* Or1 = Or0 + (size_t)8 * H_;
#pragma unroll
    for (int nt = 0; nt < 8; nt++) {
        const int c = nt * 8 + tg * 2;
        *(float2*)(Or0 + c) = make_float2(o[nt][0] * inv0, o[nt][1] * inv0);
        *(float2*)(Or1 + c) = make_float2(o[nt][2] * inv1, o[nt][3] * inv1);
    }
}

// ---------------------------------------------------------------------------
extern "C" void kernel_launch(void* const* d_in, const int* in_sizes, int n_in,
                              void* d_out, int out_size)
{
    (void)in_sizes; (void)n_in; (void)out_size;
    const float* x    = (const float*)d_in[0];
    const float* y    = (const float*)d_in[1];
    const float* bias = (const float*)d_in[2];
    const float* Wq   = (const float*)d_in[3];
    const float* Wk   = (const float*)d_in[4];
    const float* Wv   = (const float*)d_in[5];
    const float* Wo   = (const float*)d_in[6];
    float* out = (float*)d_out;

    float *Qp, *Kp, *Vp, *Tp;
    cudaGetSymbolAddress((void**)&Qp, g_Q);
    cudaGetSymbolAddress((void**)&Kp, g_K);
    cudaGetSymbolAddress((void**)&Vp, g_V);
    cudaGetSymbolAddress((void**)&Tp, g_T);

    cudaFuncSetAttribute(attn_tf32,
                         cudaFuncAttributeMaxDynamicSharedMemorySize, ATTN_SMEM);

    const float qscale = 1.0f / sqrtf((float)D_);

    dim3 qkv_grid(H_ / 128, M_ / 128, 3);   // (8, 32, 3)
    qkv_gemm<<<qkv_grid, 256>>>(x, y, Wq, Wk, Wv, Qp, Kp, Vp, qscale);

    dim3 attn_grid(L_ / 128, BH_);          // (16, 32)
    attn_tf32<<<attn_grid, 256, ATTN_SMEM>>>(Qp, Kp, Vp, bias, Tp);

    dim3 gemm_grid(H_ / 128, M_ / 128);     // (8, 32)
    out_gemm<<<gemm_grid, 256>>>(Tp, Wo, out);
}

// round 5
// speedup vs baseline: 2.8430x; 1.0075x over previous
#include <cuda_runtime.h>
#include <math.h>
#include <stdint.h>

#define B_   2
#define L_   2048
#define H_   1024
#define NH_  16
#define D_   64
#define M_   (B_ * L_)
#define BH_  (B_ * NH_)

// Scratch (device globals)
__device__ float g_Q[(size_t)BH_ * L_ * D_];   // tf32-rounded, q pre-scaled
__device__ float g_K[(size_t)BH_ * L_ * D_];
__device__ float g_V[(size_t)BH_ * L_ * D_];
__device__ float g_T[(size_t)M_ * H_];         // tf32-rounded attn output
__device__ float g_xt[(size_t)M_ * H_];        // tf32-rounded inputs/weights
__device__ float g_yt[(size_t)M_ * H_];
__device__ float g_wq[(size_t)H_ * H_];
__device__ float g_wk[(size_t)H_ * H_];
__device__ float g_wv[(size_t)H_ * H_];
__device__ float g_wo[(size_t)H_ * H_];

__device__ __forceinline__ uint32_t f2tf(float f) {
    uint32_t u;
    asm("cvt.rna.tf32.f32 %0, %1;" : "=r"(u) : "f"(f));
    return u;
}
__device__ __forceinline__ uint4 f2tf4(float4 v) {
    return make_uint4(f2tf(v.x), f2tf(v.y), f2tf(v.z), f2tf(v.w));
}
__device__ __forceinline__ void mma_tf32(float* d,
    uint32_t a0, uint32_t a1, uint32_t a2, uint32_t a3,
    uint32_t b0, uint32_t b1)
{
    asm volatile(
        "mma.sync.aligned.m16n8k8.row.col.f32.tf32.tf32.f32 "
        "{%0,%1,%2,%3}, {%4,%5,%6,%7}, {%8,%9}, {%0,%1,%2,%3};"
        : "+f"(d[0]), "+f"(d[1]), "+f"(d[2]), "+f"(d[3])
        : "r"(a0), "r"(a1), "r"(a2), "r"(a3), "r"(b0), "r"(b1));
}

// cp.async helpers
__device__ __forceinline__ void cp16(uint32_t dst, const void* src) {
    asm volatile("cp.async.cg.shared.global [%0], [%1], 16;"
                 :: "r"(dst), "l"(src));
}
__device__ __forceinline__ void cp_commit() {
    asm volatile("cp.async.commit_group;" ::: "memory");
}
__device__ __forceinline__ void cp_wait1() {
    asm volatile("cp.async.wait_group 1;" ::: "memory");
}
__device__ __forceinline__ void cp_wait0() {
    asm volatile("cp.async.wait_group 0;" ::: "memory");
}

// ---------------------------------------------------------------------------
// cvt: round fp32 buffers to tf32-in-fp32 once (blockIdx.z selects buffer)
// ---------------------------------------------------------------------------
__global__ __launch_bounds__(256) void cvt_kernel(
    const float* __restrict__ x, const float* __restrict__ y,
    const float* __restrict__ Wq, const float* __restrict__ Wk,
    const float* __restrict__ Wv, const float* __restrict__ Wo,
    float* __restrict__ xt, float* __restrict__ yt,
    float* __restrict__ wq, float* __restrict__ wk,
    float* __restrict__ wv, float* __restrict__ wo)
{
    const int z = blockIdx.z;
    const float* src; float* dst; int n;
    switch (z) {
        case 0: src = x;  dst = xt; n = M_ * H_; break;
        case 1: src = y;  dst = yt; n = M_ * H_; break;
        case 2: src = Wq; dst = wq; n = H_ * H_; break;
        case 3: src = Wk; dst = wk; n = H_ * H_; break;
        case 4: src = Wv; dst = wv; n = H_ * H_; break;
        default: src = Wo; dst = wo; n = H_ * H_; break;
    }
    const int n4 = n >> 2;
    const int stride = gridDim.x * blockDim.x;
    for (int i = blockIdx.x * blockDim.x + threadIdx.x; i < n4; i += stride)
        ((uint4*)dst)[i] = f2tf4(((const float4*)src)[i]);
}

// ---------------------------------------------------------------------------
// tf32 GEMM, cp.async 2-stage pipeline. CTA 128x128, BK=32, 256 thr.
// Operands are pre-rounded tf32 bits. mode1 epilogue rounds outputs to tf32.
// ---------------------------------------------------------------------------
#define AS_STRIDE 36
#define BS_STRIDE 136
#define GEMM_STAGE_A (128 * AS_STRIDE)
#define GEMM_STAGE_B (32 * BS_STRIDE)
#define GEMM_STAGE   (GEMM_STAGE_A + GEMM_STAGE_B)
#define GEMM_SMEM    (2 * GEMM_STAGE * 4)

__device__ __forceinline__ void gemm_load_stage(
    const float* __restrict__ A, const float* __restrict__ W,
    int K, int N, int bm, int bn, uint32_t smbase, int st, int k0, int tid)
{
    const uint32_t base = smbase + (uint32_t)(st * GEMM_STAGE) * 4u;
#pragma unroll
    for (int it = 0; it < 4; ++it) {
        const int idx = tid + it * 256;
        const int m  = idx >> 3;
        const int kq = (idx & 7) << 2;
        cp16(base + (uint32_t)(m * AS_STRIDE + kq) * 4u,
             A + (size_t)(bm + m) * K + k0 + kq);
        const int kr = idx >> 5;
        const int nq = (idx & 31) << 2;
        cp16(base + (uint32_t)(GEMM_STAGE_A + kr * BS_STRIDE + nq) * 4u,
             W + (size_t)(k0 + kr) * N + bn + nq);
    }
    cp_commit();
}

__device__ __forceinline__ void gemm_body(
    const float* __restrict__ A, const float* __restrict__ W,
    float* __restrict__ C, int K, int N, int mode, float scale,
    int bm, int bn, uint32_t* sm)
{
    const int tid  = threadIdx.x;
    const int lane = tid & 31;
    const int warp = tid >> 5;
    const int g    = lane >> 2;
    const int tg   = lane & 3;
    const int m0b  = (warp >> 1) * 32;
    const int n0b  = (warp & 1) * 64;
    const uint32_t smbase = (uint32_t)__cvta_generic_to_shared(sm);

    float acc[2][8][4];
#pragma unroll
    for (int mt = 0; mt < 2; mt++)
#pragma unroll
        for (int nt = 0; nt < 8; nt++)
#pragma unroll
            for (int r = 0; r < 4; r++) acc[mt][nt][r] = 0.f;

    gemm_load_stage(A, W, K, N, bm, bn, smbase, 0, 0, tid);

    const int niter = K / 32;
    for (int itn = 0; itn < niter; ++itn) {
        if (itn + 1 < niter) {
            gemm_load_stage(A, W, K, N, bm, bn, smbase, (itn + 1) & 1,
                            (itn + 1) * 32, tid);
            cp_wait1();
        } else {
            cp_wait0();
        }
        __syncthreads();

        uint32_t* As = sm + (itn & 1) * GEMM_STAGE;
        uint32_t* Bs = As + GEMM_STAGE_A;

#pragma unroll
        for (int ks = 0; ks < 4; ks++) {
            const int kl = ks * 8;
            uint32_t bf[8][2];
#pragma unroll
            for (int nt = 0; nt < 8; nt++) {
                const int n0 = n0b + nt * 8;
                bf[nt][0] = Bs[(kl + tg) * BS_STRIDE + n0 + g];
                bf[nt][1] = Bs[(kl + tg + 4) * BS_STRIDE + n0 + g];
            }
#pragma unroll
            for (int mt = 0; mt < 2; mt++) {
                const int m0 = m0b + mt * 16;
                uint32_t a0 = As[(m0 + g) * AS_STRIDE + kl + tg];
                uint32_t a1 = As[(m0 + g + 8) * AS_STRIDE + kl + tg];
                uint32_t a2 = As[(m0 + g) * AS_STRIDE + kl + tg + 4];
                uint32_t a3 = As[(m0 + g + 8) * AS_STRIDE + kl + tg + 4];
#pragma unroll
                for (int nt = 0; nt < 8; nt++)
                    mma_tf32(acc[mt][nt], a0, a1, a2, a3, bf[nt][0], bf[nt][1]);
            }
        }
        __syncthreads();
    }

#pragma unroll
    for (int mt = 0; mt < 2; mt++) {
        const int r1 = bm + m0b + mt * 16 + g;
#pragma unroll
        for (int nt = 0; nt < 8; nt++) {
            const int c = bn + n0b + nt * 8 + tg * 2;
            float2 v1 = make_float2(acc[mt][nt][0] * scale, acc[mt][nt][1] * scale);
            float2 v2 = make_float2(acc[mt][nt][2] * scale, acc[mt][nt][3] * scale);
            if (mode == 0) {
                *(float2*)(C + (size_t)r1 * N + c)       = v1;
                *(float2*)(C + (size_t)(r1 + 8) * N + c) = v2;
            } else {
                // head-split store, rounded to tf32 for downstream cp.async use
                const int hh = c >> 6;
                const int dd = c & 63;
                int bb = r1 / L_, l = r1 - bb * L_;
                *(uint2*)(C + (((size_t)(bb * NH_ + hh)) * L_ + l) * D_ + dd) =
                    make_uint2(f2tf(v1.x), f2tf(v1.y));
                const int r2 = r1 + 8;
                bb = r2 / L_; l = r2 - bb * L_;
                *(uint2*)(C + (((size_t)(bb * NH_ + hh)) * L_ + l) * D_ + dd) =
                    make_uint2(f2tf(v2.x), f2tf(v2.y));
            }
        }
    }
}

__global__ __launch_bounds__(256, 2) void qkv_gemm(
    const float* __restrict__ xt, const float* __restrict__ yt,
    const float* __restrict__ wq, const float* __restrict__ wk,
    const float* __restrict__ wv,
    float* __restrict__ Qd, float* __restrict__ Kd, float* __restrict__ Vd,
    float qscale)
{
    extern __shared__ uint32_t sm[];
    const int z = blockIdx.z;
    const float* A = (z == 0) ? xt : yt;
    const float* W = (z == 0) ? wq : (z == 1) ? wk : wv;
    float* C = (z == 0) ? Qd : (z == 1) ? Kd : Vd;
    const float scale = (z == 0) ? qscale : 1.0f;
    gemm_body(A, W, C, H_, H_, 1, scale, blockIdx.y * 128, blockIdx.x * 128, sm);
}

__global__ __launch_bounds__(256, 2) void out_gemm(
    const float* __restrict__ A, const float* __restrict__ W,
    float* __restrict__ C)
{
    extern __shared__ uint32_t sm[];
    gemm_body(A, W, C, H_, H_, 0, 1.0f, blockIdx.y * 128, blockIdx.x * 128, sm);
}

// ---------------------------------------------------------------------------
// Flash attention: Q in registers, K/V 64-key chunks with cp.async 2-stage
// pipeline, P via quad shuffles. CTA = 128 q-rows, 8 warps, 2 CTAs/SM.
// ---------------------------------------------------------------------------
#define KS_STR 68
#define VS_STR 72
#define KV_STAGE (64 * KS_STR + 64 * VS_STR)   // words per stage
#define ATTN_SMEM (2 * KV_STAGE * 4)

__device__ __forceinline__ void attn_load_kv(
    const float* __restrict__ Kb, const float* __restrict__ Vb,
    uint32_t smbase, int st, int kv0, int tid)
{
    const uint32_t base = smbase + (uint32_t)(st * KV_STAGE) * 4u;
#pragma unroll
    for (int it = 0; it < 4; ++it) {
        const int idx = tid + it * 256;
        const int r = idx >> 4;
        const int c = (idx & 15) << 2;
        cp16(base + (uint32_t)(r * KS_STR + c) * 4u,
             Kb + (size_t)(kv0 + r) * D_ + c);
        cp16(base + (uint32_t)(64 * KS_STR + r * VS_STR + c) * 4u,
             Vb + (size_t)(kv0 + r) * D_ + c);
    }
    cp_commit();
}

__global__ __launch_bounds__(256, 2) void attn_tf32(
    const float* __restrict__ Q, const float* __restrict__ K,
    const float* __restrict__ V, const float* __restrict__ bias,
    float* __restrict__ Out)
{
    extern __shared__ uint32_t su[];

    const int tid  = threadIdx.x;
    const int lane = tid & 31;
    const int w    = tid >> 5;
    const int g    = lane >> 2;
    const int tg   = lane & 3;
    const int bh   = blockIdx.y;
    const int q0   = blockIdx.x * 128;
    const int bb   = bh / NH_;
    const int hh   = bh - bb * NH_;

    const float* Kb = K + (size_t)bh * L_ * D_;
    const float* Vb = V + (size_t)bh * L_ * D_;
    const uint32_t* Qw = (const uint32_t*)(Q + (size_t)bh * L_ * D_);
    const uint32_t smbase = (uint32_t)__cvta_generic_to_shared(su);

    const int qrow = w * 16 + g;

    // Q fragments into registers (values already tf32-rounded)
    uint32_t qa[8][4];
#pragma unroll
    for (int ks = 0; ks < 8; ks++) {
        const int kl = ks * 8;
        qa[ks][0] = Qw[(size_t)(q0 + qrow) * D_ + kl + tg];
        qa[ks][1] = Qw[(size_t)(q0 + qrow + 8) * D_ + kl + tg];
        qa[ks][2] = Qw[(size_t)(q0 + qrow) * D_ + kl + tg + 4];
        qa[ks][3] = Qw[(size_t)(q0 + qrow + 8) * D_ + kl + tg + 4];
    }

    const int srcA = (lane & 28) | (tg >> 1);
    const bool oddtg = (tg & 1);

    float o[8][4];
#pragma unroll
    for (int n = 0; n < 8; n++)
#pragma unroll
        for (int r = 0; r < 4; r++) o[n][r] = 0.f;
    float mrun0 = -1e30f, mrun1 = -1e30f, lrun0 = 0.f, lrun1 = 0.f;

    attn_load_kv(Kb, Vb, smbase, 0, 0, tid);

    for (int ch = 0; ch < 32; ++ch) {
        if (ch + 1 < 32) {
            attn_load_kv(Kb, Vb, smbase, (ch + 1) & 1, (ch + 1) * 64, tid);
            cp_wait1();
        } else {
            cp_wait0();
        }
        __syncthreads();

        uint32_t* Ks = su + (ch & 1) * KV_STAGE;
        uint32_t* Vs = Ks + 64 * KS_STR;
        const int kv0 = ch * 64;

        // S init from bias
        float s[8][4];
#pragma unroll
        for (int j = 0; j < 8; j++) {
            const float* bp = bias + (size_t)(q0 + qrow) * L_ + kv0 + j * 8 + tg * 2;
            float2 b1 = *(const float2*)bp;
            float2 b2 = *(const float2*)(bp + (size_t)8 * L_);
            s[j][0] = b1.x; s[j][1] = b1.y; s[j][2] = b2.x; s[j][3] = b2.y;
        }

        // S += Q K^T
#pragma unroll
        for (int ks = 0; ks < 8; ks++) {
            const int kl = ks * 8;
#pragma unroll
            for (int j = 0; j < 8; j++) {
                uint32_t b0 = Ks[(j * 8 + g) * KS_STR + kl + tg];
                uint32_t b1 = Ks[(j * 8 + g) * KS_STR + kl + tg + 4];
                mma_tf32(s[j], qa[ks][0], qa[ks][1], qa[ks][2], qa[ks][3], b0, b1);
            }
        }

        // Online softmax
        float mx0 = -1e30f, mx1 = -1e30f;
#pragma unroll
        for (int j = 0; j < 8; j++) {
            mx0 = fmaxf(mx0, fmaxf(s[j][0], s[j][1]));
            mx1 = fmaxf(mx1, fmaxf(s[j][2], s[j][3]));
        }
        mx0 = fmaxf(mx0, __shfl_xor_sync(0xffffffffu, mx0, 1));
        mx0 = fmaxf(mx0, __shfl_xor_sync(0xffffffffu, mx0, 2));
        mx1 = fmaxf(mx1, __shfl_xor_sync(0xffffffffu, mx1, 1));
        mx1 = fmaxf(mx1, __shfl_xor_sync(0xffffffffu, mx1, 2));

        const float mn0 = fmaxf(mrun0, mx0);
        const float mn1 = fmaxf(mrun1, mx1);
        const float al0 = __expf(mrun0 - mn0);
        const float al1 = __expf(mrun1 - mn1);
        float sum0 = 0.f, sum1 = 0.f;
#pragma unroll
        for (int j = 0; j < 8; j++) {
            s[j][0] = __expf(s[j][0] - mn0); sum0 += s[j][0];
            s[j][1] = __expf(s[j][1] - mn0); sum0 += s[j][1];
            s[j][2] = __expf(s[j][2] - mn1); sum1 += s[j][2];
            s[j][3] = __expf(s[j][3] - mn1); sum1 += s[j][3];
        }
        sum0 += __shfl_xor_sync(0xffffffffu, sum0, 1);
        sum0 += __shfl_xor_sync(0xffffffffu, sum0, 2);
        sum1 += __shfl_xor_sync(0xffffffffu, sum1, 1);
        sum1 += __shfl_xor_sync(0xffffffffu, sum1, 2);
        lrun0 = lrun0 * al0 + sum0;
        lrun1 = lrun1 * al1 + sum1;
        mrun0 = mn0;
        mrun1 = mn1;
#pragma unroll
        for (int n = 0; n < 8; n++) {
            o[n][0] *= al0; o[n][1] *= al0;
            o[n][2] *= al1; o[n][3] *= al1;
        }

        // O += P V (P A-frags via quad shuffles)
#pragma unroll
        for (int kk = 0; kk < 8; kk++) {
            uint32_t p0 = f2tf(s[kk][0]);
            uint32_t p1 = f2tf(s[kk][1]);
            uint32_t p2 = f2tf(s[kk][2]);
            uint32_t p3 = f2tf(s[kk][3]);
            uint32_t t0, t1;
            t0 = __shfl_sync(0xffffffffu, p0, srcA);
            t1 = __shfl_sync(0xffffffffu, p1, srcA);
            const uint32_t a0 = oddtg ? t1 : t0;
            t0 = __shfl_sync(0xffffffffu, p2, srcA);
            t1 = __shfl_sync(0xffffffffu, p3, srcA);
            const uint32_t a1 = oddtg ? t1 : t0;
            t0 = __shfl_sync(0xffffffffu, p0, srcA + 2);
            t1 = __shfl_sync(0xffffffffu, p1, srcA + 2);
            const uint32_t a2 = oddtg ? t1 : t0;
            t0 = __shfl_sync(0xffffffffu, p2, srcA + 2);
            t1 = __shfl_sync(0xffffffffu, p3, srcA + 2);
            const uint32_t a3 = oddtg ? t1 : t0;

            const int kl = kk * 8;
#pragma unroll
            for (int nt = 0; nt < 8; nt++) {
                uint32_t b0 = Vs[(kl + tg) * VS_STR + nt * 8 + g];
                uint32_t b1 = Vs[(kl + tg + 4) * VS_STR + nt * 8 + g];
                mma_tf32(o[nt], a0, a1, a2, a3, b0, b1);
            }
        }
        __syncthreads();
    }

    // Write normalized output (tf32-rounded for out_gemm's cp.async path)
    const float inv0 = 1.0f / lrun0;
    const float inv1 = 1.0f / lrun1;
    uint32_t* Or0 = (uint32_t*)(Out + (size_t)(bb * L_ + q0 + qrow) * H_ + hh * D_);
    uint32_t* Or1 = Or0 + (size_t)8 * H_;
#pragma unroll
    for (int nt = 0; nt < 8; nt++) {
        const int c = nt * 8 + tg * 2;
        *(uint2*)(Or0 + c) = make_uint2(f2tf(o[nt][0] * inv0), f2tf(o[nt][1] * inv0));
        *(uint2*)(Or1 + c) = make_uint2(f2tf(o[nt][2] * inv1), f2tf(o[nt][3] * inv1));
    }
}

// ---------------------------------------------------------------------------
extern "C" void kernel_launch(void* const* d_in, const int* in_sizes, int n_in,
                              void* d_out, int out_size)
{
    (void)in_sizes; (void)n_in; (void)out_size;
    const float* x    = (const float*)d_in[0];
    const float* y    = (const float*)d_in[1];
    const float* bias = (const float*)d_in[2];
    const float* Wq   = (const float*)d_in[3];
    const float* Wk   = (const float*)d_in[4];
    const float* Wv   = (const float*)d_in[5];
    const float* Wo   = (const float*)d_in[6];
    float* out = (float*)d_out;

    float *Qp, *Kp, *Vp, *Tp, *xt, *yt, *wq, *wk, *wv, *wo;
    cudaGetSymbolAddress((void**)&Qp, g_Q);
    cudaGetSymbolAddress((void**)&Kp, g_K);
    cudaGetSymbolAddress((void**)&Vp, g_V);
    cudaGetSymbolAddress((void**)&Tp, g_T);
    cudaGetSymbolAddress((void**)&xt, g_xt);
    cudaGetSymbolAddress((void**)&yt, g_yt);
    cudaGetSymbolAddress((void**)&wq, g_wq);
    cudaGetSymbolAddress((void**)&wk, g_wk);
    cudaGetSymbolAddress((void**)&wv, g_wv);
    cudaGetSymbolAddress((void**)&wo, g_wo);

    cudaFuncSetAttribute(attn_tf32,
                         cudaFuncAttributeMaxDynamicSharedMemorySize, ATTN_SMEM);
    cudaFuncSetAttribute(qkv_gemm,
                         cudaFuncAttributeMaxDynamicSharedMemorySize, GEMM_SMEM);
    cudaFuncSetAttribute(out_gemm,
                         cudaFuncAttributeMaxDynamicSharedMemorySize, GEMM_SMEM);

    const float qscale = 1.0f / sqrtf((float)D_);

    cvt_kernel<<<dim3(128, 1, 6), 256>>>(x, y, Wq, Wk, Wv, Wo,
                                         xt, yt, wq, wk, wv, wo);

    dim3 qkv_grid(H_ / 128, M_ / 128, 3);
    qkv_gemm<<<qkv_grid, 256, GEMM_SMEM>>>(xt, yt, wq, wk, wv, Qp, Kp, Vp, qscale);

    dim3 attn_grid(L_ / 128, BH_);
    attn_tf32<<<attn_grid, 256, ATTN_SMEM>>>(Qp, Kp, Vp, bias, Tp);

    dim3 gemm_grid(H_ / 128, M_ / 128);
    out_gemm<<<gemm_grid, 256, GEMM_SMEM>>>(Tp, wo, out);
}

// round 6
// speedup vs baseline: 3.1048x; 1.0921x over previous
#include <cuda_runtime.h>
#include <math.h>
#include <stdint.h>

#define B_   2
#define L_   2048
#define H_   1024
#define NH_  16
#define D_   64
#define M_   (B_ * L_)
#define BH_  (B_ * NH_)

// Scratch (device globals)
__device__ float g_Q[(size_t)BH_ * L_ * D_];   // tf32-rounded, q pre-scaled
__device__ float g_K[(size_t)BH_ * L_ * D_];
__device__ float g_V[(size_t)BH_ * L_ * D_];
__device__ float g_T[(size_t)M_ * H_];         // tf32-rounded attn output
__device__ float g_xt[(size_t)M_ * H_];
__device__ float g_yt[(size_t)M_ * H_];
__device__ float g_wq[(size_t)H_ * H_];
__device__ float g_wk[(size_t)H_ * H_];
__device__ float g_wv[(size_t)H_ * H_];
__device__ float g_wo[(size_t)H_ * H_];

__device__ __forceinline__ uint32_t f2tf(float f) {
    uint32_t u;
    asm("cvt.rna.tf32.f32 %0, %1;" : "=r"(u) : "f"(f));
    return u;
}
__device__ __forceinline__ uint4 f2tf4(float4 v) {
    return make_uint4(f2tf(v.x), f2tf(v.y), f2tf(v.z), f2tf(v.w));
}
__device__ __forceinline__ void mma_tf32(float* d,
    uint32_t a0, uint32_t a1, uint32_t a2, uint32_t a3,
    uint32_t b0, uint32_t b1)
{
    asm volatile(
        "mma.sync.aligned.m16n8k8.row.col.f32.tf32.tf32.f32 "
        "{%0,%1,%2,%3}, {%4,%5,%6,%7}, {%8,%9}, {%0,%1,%2,%3};"
        : "+f"(d[0]), "+f"(d[1]), "+f"(d[2]), "+f"(d[3])
        : "r"(a0), "r"(a1), "r"(a2), "r"(a3), "r"(b0), "r"(b1));
}

__device__ __forceinline__ void cp16(uint32_t dst, const void* src) {
    asm volatile("cp.async.cg.shared.global [%0], [%1], 16;"
                 :: "r"(dst), "l"(src));
}
__device__ __forceinline__ void cp_commit() {
    asm volatile("cp.async.commit_group;" ::: "memory");
}
__device__ __forceinline__ void cp_wait1() {
    asm volatile("cp.async.wait_group 1;" ::: "memory");
}
__device__ __forceinline__ void cp_wait0() {
    asm volatile("cp.async.wait_group 0;" ::: "memory");
}

// ---------------------------------------------------------------------------
// cvt: round fp32 buffers to tf32-in-fp32 once
// ---------------------------------------------------------------------------
__global__ __launch_bounds__(256) void cvt_kernel(
    const float* __restrict__ x, const float* __restrict__ y,
    const float* __restrict__ Wq, const float* __restrict__ Wk,
    const float* __restrict__ Wv, const float* __restrict__ Wo,
    float* __restrict__ xt, float* __restrict__ yt,
    float* __restrict__ wq, float* __restrict__ wk,
    float* __restrict__ wv, float* __restrict__ wo)
{
    const int z = blockIdx.z;
    const float* src; float* dst; int n;
    switch (z) {
        case 0: src = x;  dst = xt; n = M_ * H_; break;
        case 1: src = y;  dst = yt; n = M_ * H_; break;
        case 2: src = Wq; dst = wq; n = H_ * H_; break;
        case 3: src = Wk; dst = wk; n = H_ * H_; break;
        case 4: src = Wv; dst = wv; n = H_ * H_; break;
        default: src = Wo; dst = wo; n = H_ * H_; break;
    }
    const int n4 = n >> 2;
    const int stride = gridDim.x * blockDim.x;
    for (int i = blockIdx.x * blockDim.x + threadIdx.x; i < n4; i += stride)
        ((uint4*)dst)[i] = f2tf4(((const float4*)src)[i]);
}

// ---------------------------------------------------------------------------
// tf32 GEMM, 3-stage cp.async. CTA 128x128, BK=32, 128 thr = 4 warps,
// warp tile 64x64 (2x2 warp grid, 4 m-tiles x 8 n-tiles per warp).
// ---------------------------------------------------------------------------
#define AS_STRIDE 36
#define BS_STRIDE 136
#define GEMM_STAGE_A (128 * AS_STRIDE)
#define GEMM_STAGE_B (32 * BS_STRIDE)
#define GEMM_STAGE   (GEMM_STAGE_A + GEMM_STAGE_B)
#define GEMM_SMEM    (3 * GEMM_STAGE * 4)

__device__ __forceinline__ void gemm_load_stage(
    const float* __restrict__ A, const float* __restrict__ W,
    int K, int N, int bm, int bn, uint32_t smbase, int st, int k0, int tid)
{
    const uint32_t base = smbase + (uint32_t)(st * GEMM_STAGE) * 4u;
#pragma unroll
    for (int it = 0; it < 8; ++it) {
        const int idx = tid + it * 128;
        const int m  = idx >> 3;
        const int kq = (idx & 7) << 2;
        cp16(base + (uint32_t)(m * AS_STRIDE + kq) * 4u,
             A + (size_t)(bm + m) * K + k0 + kq);
        const int kr = idx >> 5;
        const int nq = (idx & 31) << 2;
        cp16(base + (uint32_t)(GEMM_STAGE_A + kr * BS_STRIDE + nq) * 4u,
             W + (size_t)(k0 + kr) * N + bn + nq);
    }
    cp_commit();
}

__device__ __forceinline__ void gemm_body(
    const float* __restrict__ A, const float* __restrict__ W,
    float* __restrict__ C, int K, int N, int mode, float scale,
    int bm, int bn, uint32_t* sm)
{
    const int tid  = threadIdx.x;
    const int lane = tid & 31;
    const int warp = tid >> 5;           // 0..3
    const int g    = lane >> 2;
    const int tg   = lane & 3;
    const int m0b  = (warp >> 1) * 64;
    const int n0b  = (warp & 1) * 64;
    const uint32_t smbase = (uint32_t)__cvta_generic_to_shared(sm);

    float acc[4][8][4];
#pragma unroll
    for (int mt = 0; mt < 4; mt++)
#pragma unroll
        for (int nt = 0; nt < 8; nt++)
#pragma unroll
            for (int r = 0; r < 4; r++) acc[mt][nt][r] = 0.f;

    gemm_load_stage(A, W, K, N, bm, bn, smbase, 0, 0, tid);
    gemm_load_stage(A, W, K, N, bm, bn, smbase, 1, 32, tid);

    const int niter = K / 32;
    for (int itn = 0; itn < niter; ++itn) {
        if (itn < niter - 1) cp_wait1(); else cp_wait0();
        __syncthreads();
        if (itn + 2 < niter)
            gemm_load_stage(A, W, K, N, bm, bn, smbase, (itn + 2) % 3,
                            (itn + 2) * 32, tid);

        uint32_t* As = sm + (itn % 3) * GEMM_STAGE;
        uint32_t* Bs = As + GEMM_STAGE_A;

#pragma unroll
        for (int ks = 0; ks < 4; ks++) {
            const int kl = ks * 8;
            uint32_t bf[8][2];
#pragma unroll
            for (int nt = 0; nt < 8; nt++) {
                const int n0 = n0b + nt * 8;
                bf[nt][0] = Bs[(kl + tg) * BS_STRIDE + n0 + g];
                bf[nt][1] = Bs[(kl + tg + 4) * BS_STRIDE + n0 + g];
            }
#pragma unroll
            for (int mt = 0; mt < 4; mt++) {
                const int m0 = m0b + mt * 16;
                uint32_t a0 = As[(m0 + g) * AS_STRIDE + kl + tg];
                uint32_t a1 = As[(m0 + g + 8) * AS_STRIDE + kl + tg];
                uint32_t a2 = As[(m0 + g) * AS_STRIDE + kl + tg + 4];
                uint32_t a3 = As[(m0 + g + 8) * AS_STRIDE + kl + tg + 4];
#pragma unroll
                for (int nt = 0; nt < 8; nt++)
                    mma_tf32(acc[mt][nt], a0, a1, a2, a3, bf[nt][0], bf[nt][1]);
            }
        }
    }
    __syncthreads();

#pragma unroll
    for (int mt = 0; mt < 4; mt++) {
        const int r1 = bm + m0b + mt * 16 + g;
#pragma unroll
        for (int nt = 0; nt < 8; nt++) {
            const int c = bn + n0b + nt * 8 + tg * 2;
            float2 v1 = make_float2(acc[mt][nt][0] * scale, acc[mt][nt][1] * scale);
            float2 v2 = make_float2(acc[mt][nt][2] * scale, acc[mt][nt][3] * scale);
            if (mode == 0) {
                *(float2*)(C + (size_t)r1 * N + c)       = v1;
                *(float2*)(C + (size_t)(r1 + 8) * N + c) = v2;
            } else {
                const int hh = c >> 6;
                const int dd = c & 63;
                int bb = r1 / L_, l = r1 - bb * L_;
                *(uint2*)(C + (((size_t)(bb * NH_ + hh)) * L_ + l) * D_ + dd) =
                    make_uint2(f2tf(v1.x), f2tf(v1.y));
                const int r2 = r1 + 8;
                bb = r2 / L_; l = r2 - bb * L_;
                *(uint2*)(C + (((size_t)(bb * NH_ + hh)) * L_ + l) * D_ + dd) =
                    make_uint2(f2tf(v2.x), f2tf(v2.y));
            }
        }
    }
}

__global__ __launch_bounds__(128, 2) void qkv_gemm(
    const float* __restrict__ xt, const float* __restrict__ yt,
    const float* __restrict__ wq, const float* __restrict__ wk,
    const float* __restrict__ wv,
    float* __restrict__ Qd, float* __restrict__ Kd, float* __restrict__ Vd,
    float qscale)
{
    extern __shared__ uint32_t sm[];
    const int z = blockIdx.z;
    const float* A = (z == 0) ? xt : yt;
    const float* W = (z == 0) ? wq : (z == 1) ? wk : wv;
    float* C = (z == 0) ? Qd : (z == 1) ? Kd : Vd;
    const float scale = (z == 0) ? qscale : 1.0f;
    gemm_body(A, W, C, H_, H_, 1, scale, blockIdx.y * 128, blockIdx.x * 128, sm);
}

__global__ __launch_bounds__(128, 2) void out_gemm(
    const float* __restrict__ A, const float* __restrict__ W,
    float* __restrict__ C)
{
    extern __shared__ uint32_t sm[];
    gemm_body(A, W, C, H_, H_, 0, 1.0f, blockIdx.y * 128, blockIdx.x * 128, sm);
}

// ---------------------------------------------------------------------------
// Flash attention: 4 warps x 32 q-rows, Q in registers, K/V 64-key chunks,
// 3-stage cp.async, P via quad shuffles. CTA = 128 q-rows, 2 CTAs/SM.
// ---------------------------------------------------------------------------
#define KS_STR 68
#define VS_STR 72
#define KV_STAGE (64 * KS_STR + 64 * VS_STR)   // words per stage
#define ATTN_SMEM (3 * KV_STAGE * 4)

__device__ __forceinline__ void attn_load_kv(
    const float* __restrict__ Kb, const float* __restrict__ Vb,
    uint32_t smbase, int st, int kv0, int tid)
{
    const uint32_t base = smbase + (uint32_t)(st * KV_STAGE) * 4u;
#pragma unroll
    for (int it = 0; it < 8; ++it) {
        const int idx = tid + it * 128;
        const int r = idx >> 4;
        const int c = (idx & 15) << 2;
        cp16(base + (uint32_t)(r * KS_STR + c) * 4u,
             Kb + (size_t)(kv0 + r) * D_ + c);
        cp16(base + (uint32_t)(64 * KS_STR + r * VS_STR + c) * 4u,
             Vb + (size_t)(kv0 + r) * D_ + c);
    }
    cp_commit();
}

__global__ __launch_bounds__(128, 2) void attn_tf32(
    const float* __restrict__ Q, const float* __restrict__ K,
    const float* __restrict__ V, const float* __restrict__ bias,
    float* __restrict__ Out)
{
    extern __shared__ uint32_t su[];

    const int tid  = threadIdx.x;
    const int lane = tid & 31;
    const int w    = tid >> 5;           // 0..3
    const int g    = lane >> 2;
    const int tg   = lane & 3;
    const int bh   = blockIdx.y;
    const int q0   = blockIdx.x * 128;
    const int bb   = bh / NH_;
    const int hh   = bh - bb * NH_;

    const float* Kb = K + (size_t)bh * L_ * D_;
    const float* Vb = V + (size_t)bh * L_ * D_;
    const uint32_t* Qw = (const uint32_t*)(Q + (size_t)bh * L_ * D_);
    const uint32_t smbase = (uint32_t)__cvta_generic_to_shared(su);

    const int qbase = w * 32;

    // Q fragments (already tf32-rounded): 2 m-tiles x 8 k-steps
    uint32_t qa[8][2][4];
#pragma unroll
    for (int ks = 0; ks < 8; ks++) {
        const int kl = ks * 8;
#pragma unroll
        for (int mt = 0; mt < 2; mt++) {
            const int r0 = q0 + qbase + mt * 16 + g;
            qa[ks][mt][0] = Qw[(size_t)r0 * D_ + kl + tg];
            qa[ks][mt][1] = Qw[(size_t)(r0 + 8) * D_ + kl + tg];
            qa[ks][mt][2] = Qw[(size_t)r0 * D_ + kl + tg + 4];
            qa[ks][mt][3] = Qw[(size_t)(r0 + 8) * D_ + kl + tg + 4];
        }
    }

    const int srcA = (lane & 28) | (tg >> 1);
    const bool oddtg = (tg & 1);

    float o[2][8][4];
#pragma unroll
    for (int mt = 0; mt < 2; mt++)
#pragma unroll
        for (int n = 0; n < 8; n++)
#pragma unroll
            for (int r = 0; r < 4; r++) o[mt][n][r] = 0.f;
    float mrun[2][2] = {{-1e30f, -1e30f}, {-1e30f, -1e30f}};
    float lrun[2][2] = {{0.f, 0.f}, {0.f, 0.f}};

    attn_load_kv(Kb, Vb, smbase, 0, 0, tid);
    attn_load_kv(Kb, Vb, smbase, 1, 64, tid);

    for (int ch = 0; ch < 32; ++ch) {
        if (ch < 31) cp_wait1(); else cp_wait0();
        __syncthreads();
        if (ch + 2 < 32)
            attn_load_kv(Kb, Vb, smbase, (ch + 2) % 3, (ch + 2) * 64, tid);

        uint32_t* Ks = su + (ch % 3) * KV_STAGE;
        uint32_t* Vs = Ks + 64 * KS_STR;
        const int kv0 = ch * 64;

        // S init from bias
        float s[2][8][4];
#pragma unroll
        for (int mt = 0; mt < 2; mt++) {
            const int r0 = q0 + qbase + mt * 16 + g;
#pragma unroll
            for (int j = 0; j < 8; j++) {
                const float* bp = bias + (size_t)r0 * L_ + kv0 + j * 8 + tg * 2;
                float2 b1 = *(const float2*)bp;
                float2 b2 = *(const float2*)(bp + (size_t)8 * L_);
                s[mt][j][0] = b1.x; s[mt][j][1] = b1.y;
                s[mt][j][2] = b2.x; s[mt][j][3] = b2.y;
            }
        }

        // S += Q K^T
#pragma unroll
        for (int ks = 0; ks < 8; ks++) {
            const int kl = ks * 8;
#pragma unroll
            for (int j = 0; j < 8; j++) {
                uint32_t b0 = Ks[(j * 8 + g) * KS_STR + kl + tg];
                uint32_t b1 = Ks[(j * 8 + g) * KS_STR + kl + tg + 4];
#pragma unroll
                for (int mt = 0; mt < 2; mt++)
                    mma_tf32(s[mt][j], qa[ks][mt][0], qa[ks][mt][1],
                             qa[ks][mt][2], qa[ks][mt][3], b0, b1);
            }
        }

        // Online softmax per m-tile (row pairs g and g+8)
#pragma unroll
        for (int mt = 0; mt < 2; mt++) {
            float mx0 = -1e30f, mx1 = -1e30f;
#pragma unroll
            for (int j = 0; j < 8; j++) {
                mx0 = fmaxf(mx0, fmaxf(s[mt][j][0], s[mt][j][1]));
                mx1 = fmaxf(mx1, fmaxf(s[mt][j][2], s[mt][j][3]));
            }
            mx0 = fmaxf(mx0, __shfl_xor_sync(0xffffffffu, mx0, 1));
            mx0 = fmaxf(mx0, __shfl_xor_sync(0xffffffffu, mx0, 2));
            mx1 = fmaxf(mx1, __shfl_xor_sync(0xffffffffu, mx1, 1));
            mx1 = fmaxf(mx1, __shfl_xor_sync(0xffffffffu, mx1, 2));

            const float mn0 = fmaxf(mrun[mt][0], mx0);
            const float mn1 = fmaxf(mrun[mt][1], mx1);
            const float al0 = __expf(mrun[mt][0] - mn0);
            const float al1 = __expf(mrun[mt][1] - mn1);
            float sum0 = 0.f, sum1 = 0.f;
#pragma unroll
            for (int j = 0; j < 8; j++) {
                s[mt][j][0] = __expf(s[mt][j][0] - mn0); sum0 += s[mt][j][0];
                s[mt][j][1] = __expf(s[mt][j][1] - mn0); sum0 += s[mt][j][1];
                s[mt][j][2] = __expf(s[mt][j][2] - mn1); sum1 += s[mt][j][2];
                s[mt][j][3] = __expf(s[mt][j][3] - mn1); sum1 += s[mt][j][3];
            }
            sum0 += __shfl_xor_sync(0xffffffffu, sum0, 1);
            sum0 += __shfl_xor_sync(0xffffffffu, sum0, 2);
            sum1 += __shfl_xor_sync(0xffffffffu, sum1, 1);
            sum1 += __shfl_xor_sync(0xffffffffu, sum1, 2);
            lrun[mt][0] = lrun[mt][0] * al0 + sum0;
            lrun[mt][1] = lrun[mt][1] * al1 + sum1;
            mrun[mt][0] = mn0;
            mrun[mt][1] = mn1;
#pragma unroll
            for (int n = 0; n < 8; n++) {
                o[mt][n][0] *= al0; o[mt][n][1] *= al0;
                o[mt][n][2] *= al1; o[mt][n][3] *= al1;
            }
        }

        // O += P V (P A-frags via quad shuffles, V-frags shared across mt)
#pragma unroll
        for (int kk = 0; kk < 8; kk++) {
            uint32_t af[2][4];
#pragma unroll
            for (int mt = 0; mt < 2; mt++) {
                uint32_t p0 = f2tf(s[mt][kk][0]);
                uint32_t p1 = f2tf(s[mt][kk][1]);
                uint32_t p2 = f2tf(s[mt][kk][2]);
                uint32_t p3 = f2tf(s[mt][kk][3]);
                uint32_t t0, t1;
                t0 = __shfl_sync(0xffffffffu, p0, srcA);
                t1 = __shfl_sync(0xffffffffu, p1, srcA);
                af[mt][0] = oddtg ? t1 : t0;
                t0 = __shfl_sync(0xffffffffu, p2, srcA);
                t1 = __shfl_sync(0xffffffffu, p3, srcA);
                af[mt][1] = oddtg ? t1 : t0;
                t0 = __shfl_sync(0xffffffffu, p0, srcA + 2);
                t1 = __shfl_sync(0xffffffffu, p1, srcA + 2);
                af[mt][2] = oddtg ? t1 : t0;
                t0 = __shfl_sync(0xffffffffu, p2, srcA + 2);
                t1 = __shfl_sync(0xffffffffu, p3, srcA + 2);
                af[mt][3] = oddtg ? t1 : t0;
            }
            const int kl = kk * 8;
#pragma unroll
            for (int nt = 0; nt < 8; nt++) {
                uint32_t b0 = Vs[(kl + tg) * VS_STR + nt * 8 + g];
                uint32_t b1 = Vs[(kl + tg + 4) * VS_STR + nt * 8 + g];
#pragma unroll
                for (int mt = 0; mt < 2; mt++)
                    mma_tf32(o[mt][nt], af[mt][0], af[mt][1], af[mt][2],
                             af[mt][3], b0, b1);
            }
        }
    }

    // Write normalized output (tf32-rounded for out_gemm)
#pragma unroll
    for (int mt = 0; mt < 2; mt++) {
        const int r0 = q0 + qbase + mt * 16 + g;
        const float inv0 = 1.0f / lrun[mt][0];
        const float inv1 = 1.0f / lrun[mt][1];
        uint32_t* Or0 = (uint32_t*)(Out + (size_t)(bb * L_ + r0) * H_ + hh * D_);
        uint32_t* Or1 = Or0 + (size_t)8 * H_;
#pragma unroll
        for (int nt = 0; nt < 8; nt++) {
            const int c = nt * 8 + tg * 2;
            *(uint2*)(Or0 + c) =
                make_uint2(f2tf(o[mt][nt][0] * inv0), f2tf(o[mt][nt][1] * inv0));
            *(uint2*)(Or1 + c) =
                make_uint2(f2tf(o[mt][nt][2] * inv1), f2tf(o[mt][nt][3] * inv1));
        }
    }
}

// ---------------------------------------------------------------------------
extern "C" void kernel_launch(void* const* d_in, const int* in_sizes, int n_in,
                              void* d_out, int out_size)
{
    (void)in_sizes; (void)n_in; (void)out_size;
    const float* x    = (const float*)d_in[0];
    const float* y    = (const float*)d_in[1];
    const float* bias = (const float*)d_in[2];
    const float* Wq   = (const float*)d_in[3];
    const float* Wk   = (const float*)d_in[4];
    const float* Wv   = (const float*)d_in[5];
    const float* Wo   = (const float*)d_in[6];
    float* out = (float*)d_out;

    float *Qp, *Kp, *Vp, *Tp, *xt, *yt, *wq, *wk, *wv, *wo;
    cudaGetSymbolAddress((void**)&Qp, g_Q);
    cudaGetSymbolAddress((void**)&Kp, g_K);
    cudaGetSymbolAddress((void**)&Vp, g_V);
    cudaGetSymbolAddress((void**)&Tp, g_T);
    cudaGetSymbolAddress((void**)&xt, g_xt);
    cudaGetSymbolAddress((void**)&yt, g_yt);
    cudaGetSymbolAddress((void**)&wq, g_wq);
    cudaGetSymbolAddress((void**)&wk, g_wk);
    cudaGetSymbolAddress((void**)&wv, g_wv);
    cudaGetSymbolAddress((void**)&wo, g_wo);

    cudaFuncSetAttribute(attn_tf32,
                         cudaFuncAttributeMaxDynamicSharedMemorySize, ATTN_SMEM);
    cudaFuncSetAttribute(qkv_gemm,
                         cudaFuncAttributeMaxDynamicSharedMemorySize, GEMM_SMEM);
    cudaFuncSetAttribute(out_gemm,
                         cudaFuncAttributeMaxDynamicSharedMemorySize, GEMM_SMEM);

    const float qscale = 1.0f / sqrtf((float)D_);

    cvt_kernel<<<dim3(128, 1, 6), 256>>>(x, y, Wq, Wk, Wv, Wo,
                                         xt, yt, wq, wk, wv, wo);

    dim3 qkv_grid(H_ / 128, M_ / 128, 3);
    qkv_gemm<<<qkv_grid, 128, GEMM_SMEM>>>(xt, yt, wq, wk, wv, Qp, Kp, Vp, qscale);

    dim3 attn_grid(L_ / 128, BH_);
    attn_tf32<<<attn_grid, 128, ATTN_SMEM>>>(Qp, Kp, Vp, bias, Tp);

    dim3 gemm_grid(H_ / 128, M_ / 128);
    out_gemm<<<gemm_grid, 128, GEMM_SMEM>>>(Tp, wo, out);
}

// round 8
// speedup vs baseline: 4.7529x; 1.5309x over previous
#include <cuda_runtime.h>
#include <cuda_fp16.h>
#include <math.h>
#include <stdint.h>

#define B_   2
#define L_   2048
#define H_   1024
#define NH_  16
#define D_   64
#define M_   (B_ * L_)
#define BH_  (B_ * NH_)

// Scratch (device globals) — fp16 operands everywhere
__device__ __half g_Q[(size_t)BH_ * L_ * D_];   // [bh][l][d], q pre-scaled
__device__ __half g_K[(size_t)BH_ * L_ * D_];   // [bh][l][d]
__device__ __half g_V[(size_t)BH_ * D_ * L_];   // [bh][d][l]  (transposed!)
__device__ __half g_T[(size_t)M_ * H_];         // attn out, [token][H]
__device__ __half g_xh[(size_t)M_ * H_];
__device__ __half g_yh[(size_t)M_ * H_];
__device__ __half g_wqT[(size_t)H_ * H_];       // W^T, [n][k]
__device__ __half g_wkT[(size_t)H_ * H_];
__device__ __half g_wvT[(size_t)H_ * H_];
__device__ __half g_woT[(size_t)H_ * H_];

__device__ __forceinline__ uint32_t pack_h2(float a, float b) {
    __half2 h = __floats2half2_rn(a, b);
    return *(uint32_t*)&h;
}
__device__ __forceinline__ void mma_f16(float* d,
    uint32_t a0, uint32_t a1, uint32_t a2, uint32_t a3,
    uint32_t b0, uint32_t b1)
{
    asm volatile(
        "mma.sync.aligned.m16n8k16.row.col.f32.f16.f16.f32 "
        "{%0,%1,%2,%3}, {%4,%5,%6,%7}, {%8,%9}, {%0,%1,%2,%3};"
        : "+f"(d[0]), "+f"(d[1]), "+f"(d[2]), "+f"(d[3])
        : "r"(a0), "r"(a1), "r"(a2), "r"(a3), "r"(b0), "r"(b1));
}

__device__ __forceinline__ void cp16(uint32_t dst, const void* src) {
    asm volatile("cp.async.cg.shared.global [%0], [%1], 16;"
                 :: "r"(dst), "l"(src));
}
__device__ __forceinline__ void cp_commit() {
    asm volatile("cp.async.commit_group;" ::: "memory");
}
__device__ __forceinline__ void cp_wait1() {
    asm volatile("cp.async.wait_group 1;" ::: "memory");
}
__device__ __forceinline__ void cp_wait0() {
    asm volatile("cp.async.wait_group 0;" ::: "memory");
}

// ---------------------------------------------------------------------------
// cvt: x,y fp32 -> fp16
// ---------------------------------------------------------------------------
__global__ __launch_bounds__(256) void cvt_xy(
    const float* __restrict__ x, const float* __restrict__ y,
    __half* __restrict__ xh, __half* __restrict__ yh)
{
    const float* src = blockIdx.z == 0 ? x : y;
    __half* dst = blockIdx.z == 0 ? xh : yh;
    const int n4 = (M_ * H_) >> 2;
    const int stride = gridDim.x * blockDim.x;
    for (int i = blockIdx.x * blockDim.x + threadIdx.x; i < n4; i += stride) {
        float4 v = ((const float4*)src)[i];
        uint2 o;
        o.x = pack_h2(v.x, v.y);
        o.y = pack_h2(v.z, v.w);
        ((uint2*)dst)[i] = o;
    }
}

// ---------------------------------------------------------------------------
// Weight transpose + fp16: WT[n][k] = h(W[k][n])
// ---------------------------------------------------------------------------
__global__ __launch_bounds__(256) void wtrans(
    const float* __restrict__ Wq, const float* __restrict__ Wk,
    const float* __restrict__ Wv, const float* __restrict__ Wo,
    __half* __restrict__ wqT, __half* __restrict__ wkT,
    __half* __restrict__ wvT, __half* __restrict__ woT)
{
    __shared__ float tile[32][33];
    const int z = blockIdx.z;
    const float* src = (z == 0) ? Wq : (z == 1) ? Wk : (z == 2) ? Wv : Wo;
    __half* dst = (z == 0) ? wqT : (z == 1) ? wkT : (z == 2) ? wvT : woT;
    const int tx = threadIdx.x & 31;
    const int ty = threadIdx.x >> 5;
    const int bx = blockIdx.x * 32;
    const int by = blockIdx.y * 32;
#pragma unroll
    for (int i = 0; i < 32; i += 8)
        tile[ty + i][tx] = src[(size_t)(by + ty + i) * H_ + bx + tx];
    __syncthreads();
#pragma unroll
    for (int i = 0; i < 32; i += 8)
        dst[(size_t)(bx + ty + i) * H_ + by + tx] = __float2half_rn(tile[tx][ty + i]);
}

// ---------------------------------------------------------------------------
// fp16 GEMM: C[128x128] = A[M,K] @ WT[N,K]^T. 128 thr, 4 warps (2x2),
// warp 64x64, BK=32 halves, 3-stage cp.async.
// Smem tile row stride = 40 halves (20 h2, 80B): banks (20r+tg)%32 bijective.
// ---------------------------------------------------------------------------
#define G_STR 20                       // h2 per row
#define G_TILE_W (128 * G_STR)         // words per tile (2560)
#define G_STAGE_W (2 * G_TILE_W)       // 5120 words = 20480 B
#define G_SMEM (3 * G_STAGE_W * 4)

__device__ __forceinline__ void gh_load(
    const __half* __restrict__ A, const __half* __restrict__ Wt,
    uint32_t smb, int st, int k0, int bm, int bn, int tid)
{
    const uint32_t base = smb + (uint32_t)(st * G_STAGE_W * 4);
#pragma unroll
    for (int it = 0; it < 4; ++it) {
        const int idx = tid + it * 128;
        const int row = idx >> 2, ch = idx & 3;
        cp16(base + (uint32_t)(row * 80 + ch * 16),
             A + (size_t)(bm + row) * H_ + k0 + ch * 8);
    }
#pragma unroll
    for (int it = 0; it < 4; ++it) {
        const int idx = tid + it * 128;
        const int row = idx >> 2, ch = idx & 3;
        cp16(base + (uint32_t)(G_TILE_W * 4 + row * 80 + ch * 16),
             Wt + (size_t)(bn + row) * H_ + k0 + ch * 8);
    }
    cp_commit();
}

// mode 0: fp32 [M][H] store. mode 1: fp16 head-split [bh][l][d] (scaled).
// mode 2: fp16 head-split transposed [bh][d][l].
__device__ void gemm_h_body(
    const __half* __restrict__ A, const __half* __restrict__ Wt,
    float* __restrict__ Cf, __half* __restrict__ Ch,
    int mode, float scale, uint32_t* sm)
{
    const int tid  = threadIdx.x;
    const int lane = tid & 31;
    const int warp = tid >> 5;
    const int g    = lane >> 2;
    const int tg   = lane & 3;
    const int m0b  = (warp >> 1) * 64;
    const int n0b  = (warp & 1) * 64;
    const int bm   = blockIdx.y * 128;
    const int bn   = blockIdx.x * 128;
    const uint32_t smb = (uint32_t)__cvta_generic_to_shared(sm);

    float acc[4][8][4];
#pragma unroll
    for (int mt = 0; mt < 4; mt++)
#pragma unroll
        for (int nt = 0; nt < 8; nt++)
#pragma unroll
            for (int r = 0; r < 4; r++) acc[mt][nt][r] = 0.f;

    gh_load(A, Wt, smb, 0, 0,  bm, bn, tid);
    gh_load(A, Wt, smb, 1, 32, bm, bn, tid);

    for (int itn = 0; itn < 32; ++itn) {
        if (itn < 31) cp_wait1(); else cp_wait0();
        __syncthreads();
        if (itn + 2 < 32)
            gh_load(A, Wt, smb, (itn + 2) % 3, (itn + 2) * 32, bm, bn, tid);

        uint32_t* As = sm + (itn % 3) * G_STAGE_W;
        uint32_t* Bs = As + G_TILE_W;

#pragma unroll
        for (int ks = 0; ks < 2; ks++) {
            const int kl = ks * 8;
            uint32_t bf[8][2];
#pragma unroll
            for (int nt = 0; nt < 8; nt++) {
                const int nr = n0b + nt * 8 + g;
                bf[nt][0] = Bs[nr * G_STR + kl + tg];
                bf[nt][1] = Bs[nr * G_STR + kl + tg + 4];
            }
#pragma unroll
            for (int mt = 0; mt < 4; mt++) {
                const int m0 = m0b + mt * 16;
                uint32_t a0 = As[(m0 + g) * G_STR + kl + tg];
                uint32_t a1 = As[(m0 + g + 8) * G_STR + kl + tg];
                uint32_t a2 = As[(m0 + g) * G_STR + kl + tg + 4];
                uint32_t a3 = As[(m0 + g + 8) * G_STR + kl + tg + 4];
#pragma unroll
                for (int nt = 0; nt < 8; nt++)
                    mma_f16(acc[mt][nt], a0, a1, a2, a3, bf[nt][0], bf[nt][1]);
            }
        }
    }

#pragma unroll
    for (int mt = 0; mt < 4; mt++) {
        const int r1 = bm + m0b + mt * 16 + g;
        const int r2 = r1 + 8;
#pragma unroll
        for (int nt = 0; nt < 8; nt++) {
            const int c = bn + n0b + nt * 8 + tg * 2;
            float2 v1 = make_float2(acc[mt][nt][0] * scale, acc[mt][nt][1] * scale);
            float2 v2 = make_float2(acc[mt][nt][2] * scale, acc[mt][nt][3] * scale);
            if (mode == 0) {
                *(float2*)(Cf + (size_t)r1 * H_ + c) = v1;
                *(float2*)(Cf + (size_t)r2 * H_ + c) = v2;
            } else {
                const int hh = c >> 6;
                const int dd = c & 63;
                const int b1b = r1 >> 11, l1 = r1 & (L_ - 1);
                const int b2b = r2 >> 11, l2 = r2 & (L_ - 1);
                if (mode == 1) {
                    *(uint32_t*)(Ch + (((size_t)(b1b * NH_ + hh)) * L_ + l1) * D_ + dd) =
                        pack_h2(v1.x, v1.y);
                    *(uint32_t*)(Ch + (((size_t)(b2b * NH_ + hh)) * L_ + l2) * D_ + dd) =
                        pack_h2(v2.x, v2.y);
                } else {
                    __half* base1 = Ch + ((size_t)(b1b * NH_ + hh) * D_ + dd) * L_;
                    base1[l1]      = __float2half_rn(v1.x);
                    base1[L_ + l1] = __float2half_rn(v1.y);
                    __half* base2 = Ch + ((size_t)(b2b * NH_ + hh) * D_ + dd) * L_;
                    base2[l2]      = __float2half_rn(v2.x);
                    base2[L_ + l2] = __float2half_rn(v2.y);
                }
            }
        }
    }
}

__global__ __launch_bounds__(128, 2) void qkv_gemm(
    const __half* __restrict__ xh, const __half* __restrict__ yh,
    const __half* __restrict__ wqT, const __half* __restrict__ wkT,
    const __half* __restrict__ wvT,
    __half* __restrict__ Qd, __half* __restrict__ Kd, __half* __restrict__ Vd,
    float qscale)
{
    extern __shared__ uint32_t sm[];
    const int z = blockIdx.z;
    const __half* A  = (z == 0) ? xh : yh;
    const __half* Wt = (z == 0) ? wqT : (z == 1) ? wkT : wvT;
    __half* C = (z == 0) ? Qd : (z == 1) ? Kd : Vd;
    gemm_h_body(A, Wt, nullptr, C, (z == 2) ? 2 : 1,
                (z == 0) ? qscale : 1.0f, sm);
}

__global__ __launch_bounds__(128, 2) void out_gemm(
    const __half* __restrict__ A, const __half* __restrict__ woT,
    float* __restrict__ C)
{
    extern __shared__ uint32_t sm[];
    gemm_h_body(A, woT, C, nullptr, 0, 1.0f, sm);
}

// ---------------------------------------------------------------------------
// fp16 flash attention: 4 warps x 32 q-rows, Q in regs, 64-key chunks,
// 3-stage cp.async. K tile [key][d], V tile [d][key] (both 64x64 halves,
// row stride 36 h2 = 144B; banks (4r+tg)%32 bijective).
// P C-frag == PV A-frag layout in fp16: no shuffles.
// ---------------------------------------------------------------------------
#define A_STR 36                        // h2 per row
#define A_TILE_W (64 * A_STR)           // 2304 words
#define A_STAGE_W (2 * A_TILE_W)        // 4608 words = 18432 B
#define ATTN_SMEM (3 * A_STAGE_W * 4)

__device__ __forceinline__ void attn_load_kv(
    const __half* __restrict__ Kb, const __half* __restrict__ Vb,
    uint32_t smb, int st, int kv0, int tid)
{
    const uint32_t base = smb + (uint32_t)(st * A_STAGE_W * 4);
#pragma unroll
    for (int it = 0; it < 4; ++it) {
        const int idx = tid + it * 128;
        const int row = idx >> 3, ch = idx & 7;
        cp16(base + (uint32_t)(row * 144 + ch * 16),
             Kb + (size_t)(kv0 + row) * D_ + ch * 8);
    }
#pragma unroll
    for (int it = 0; it < 4; ++it) {
        const int idx = tid + it * 128;
        const int row = idx >> 3, ch = idx & 7;
        cp16(base + (uint32_t)(A_TILE_W * 4 + row * 144 + ch * 16),
             Vb + (size_t)row * L_ + kv0 + ch * 8);
    }
    cp_commit();
}

__global__ __launch_bounds__(128, 2) void attn_h(
    const __half* __restrict__ Q, const __half* __restrict__ K,
    const __half* __restrict__ V, const float* __restrict__ bias,
    __half* __restrict__ Out)
{
    extern __shared__ uint32_t su[];

    const int tid  = threadIdx.x;
    const int lane = tid & 31;
    const int w    = tid >> 5;
    const int g    = lane >> 2;
    const int tg   = lane & 3;
    const int bh   = blockIdx.y;
    const int q0   = blockIdx.x * 128;
    const int bb   = bh / NH_;
    const int hh   = bh - bb * NH_;

    const __half* Kb = K + (size_t)bh * L_ * D_;
    const __half* Vb = V + (size_t)bh * D_ * L_;
    const uint32_t* Qh2 = (const uint32_t*)(Q + (size_t)bh * L_ * D_);
    const uint32_t smb = (uint32_t)__cvta_generic_to_shared(su);

    const int qbase = w * 32;

    // Q A-fragments: 4 ksteps (k16) x 2 m-tiles x 4 regs
    uint32_t qa[4][2][4];
#pragma unroll
    for (int ks = 0; ks < 4; ks++) {
        const int kl = ks * 8;
#pragma unroll
        for (int mt = 0; mt < 2; mt++) {
            const int r0 = q0 + qbase + mt * 16 + g;
            qa[ks][mt][0] = Qh2[(size_t)r0 * 32 + kl + tg];
            qa[ks][mt][1] = Qh2[(size_t)(r0 + 8) * 32 + kl + tg];
            qa[ks][mt][2] = Qh2[(size_t)r0 * 32 + kl + tg + 4];
            qa[ks][mt][3] = Qh2[(size_t)(r0 + 8) * 32 + kl + tg + 4];
        }
    }

    float o[2][8][4];
#pragma unroll
    for (int mt = 0; mt < 2; mt++)
#pragma unroll
        for (int n = 0; n < 8; n++)
#pragma unroll
            for (int r = 0; r < 4; r++) o[mt][n][r] = 0.f;
    float mrun[2][2] = {{-1e30f, -1e30f}, {-1e30f, -1e30f}};
    float lrun[2][2] = {{0.f, 0.f}, {0.f, 0.f}};

    attn_load_kv(Kb, Vb, smb, 0, 0, tid);
    attn_load_kv(Kb, Vb, smb, 1, 64, tid);

    for (int ch = 0; ch < 32; ++ch) {
        if (ch < 31) cp_wait1(); else cp_wait0();
        __syncthreads();
        if (ch + 2 < 32)
            attn_load_kv(Kb, Vb, smb, (ch + 2) % 3, (ch + 2) * 64, tid);

        uint32_t* Ks = su + (ch % 3) * A_STAGE_W;
        uint32_t* Vs = Ks + A_TILE_W;
        const int kv0 = ch * 64;

        // S init from bias
        float s[2][8][4];
#pragma unroll
        for (int mt = 0; mt < 2; mt++) {
            const int r0 = q0 + qbase + mt * 16 + g;
#pragma unroll
            for (int j = 0; j < 8; j++) {
                const float* bp = bias + (size_t)r0 * L_ + kv0 + j * 8 + tg * 2;
                float2 b1 = *(const float2*)bp;
                float2 b2 = *(const float2*)(bp + (size_t)8 * L_);
                s[mt][j][0] = b1.x; s[mt][j][1] = b1.y;
                s[mt][j][2] = b2.x; s[mt][j][3] = b2.y;
            }
        }

        // S += Q K^T  (4 k16 steps over D=64)
#pragma unroll
        for (int ks = 0; ks < 4; ks++) {
            const int kl = ks * 8;
#pragma unroll
            for (int j = 0; j < 8; j++) {
                const int kr = (j * 8 + g) * A_STR;
                uint32_t b0 = Ks[kr + kl + tg];
                uint32_t b1 = Ks[kr + kl + tg + 4];
#pragma unroll
                for (int mt = 0; mt < 2; mt++)
                    mma_f16(s[mt][j], qa[ks][mt][0], qa[ks][mt][1],
                            qa[ks][mt][2], qa[ks][mt][3], b0, b1);
            }
        }

        // Online softmax
#pragma unroll
        for (int mt = 0; mt < 2; mt++) {
            float mx0 = -1e30f, mx1 = -1e30f;
#pragma unroll
            for (int j = 0; j < 8; j++) {
                mx0 = fmaxf(mx0, fmaxf(s[mt][j][0], s[mt][j][1]));
                mx1 = fmaxf(mx1, fmaxf(s[mt][j][2], s[mt][j][3]));
            }
            mx0 = fmaxf(mx0, __shfl_xor_sync(0xffffffffu, mx0, 1));
            mx0 = fmaxf(mx0, __shfl_xor_sync(0xffffffffu, mx0, 2));
            mx1 = fmaxf(mx1, __shfl_xor_sync(0xffffffffu, mx1, 1));
            mx1 = fmaxf(mx1, __shfl_xor_sync(0xffffffffu, mx1, 2));

            const float mn0 = fmaxf(mrun[mt][0], mx0);
            const float mn1 = fmaxf(mrun[mt][1], mx1);
            const float al0 = __expf(mrun[mt][0] - mn0);
            const float al1 = __expf(mrun[mt][1] - mn1);
            float sum0 = 0.f, sum1 = 0.f;
#pragma unroll
            for (int j = 0; j < 8; j++) {
                s[mt][j][0] = __expf(s[mt][j][0] - mn0); sum0 += s[mt][j][0];
                s[mt][j][1] = __expf(s[mt][j][1] - mn0); sum0 += s[mt][j][1];
                s[mt][j][2] = __expf(s[mt][j][2] - mn1); sum1 += s[mt][j][2];
                s[mt][j][3] = __expf(s[mt][j][3] - mn1); sum1 += s[mt][j][3];
            }
            sum0 += __shfl_xor_sync(0xffffffffu, sum0, 1);
            sum0 += __shfl_xor_sync(0xffffffffu, sum0, 2);
            sum1 += __shfl_xor_sync(0xffffffffu, sum1, 1);
            sum1 += __shfl_xor_sync(0xffffffffu, sum1, 2);
            lrun[mt][0] = lrun[mt][0] * al0 + sum0;
            lrun[mt][1] = lrun[mt][1] * al1 + sum1;
            mrun[mt][0] = mn0;
            mrun[mt][1] = mn1;
#pragma unroll
            for (int n = 0; n < 8; n++) {
                o[mt][n][0] *= al0; o[mt][n][1] *= al0;
                o[mt][n][2] *= al1; o[mt][n][3] *= al1;
            }
        }

        // O += P V : fp16 C-frag == A-frag layout, just pack
#pragma unroll
        for (int kk = 0; kk < 4; kk++) {
            uint32_t af[2][4];
#pragma unroll
            for (int mt = 0; mt < 2; mt++) {
                af[mt][0] = pack_h2(s[mt][2 * kk][0],     s[mt][2 * kk][1]);
                af[mt][1] = pack_h2(s[mt][2 * kk][2],     s[mt][2 * kk][3]);
                af[mt][2] = pack_h2(s[mt][2 * kk + 1][0], s[mt][2 * kk + 1][1]);
                af[mt][3] = pack_h2(s[mt][2 * kk + 1][2], s[mt][2 * kk + 1][3]);
            }
            const int kl = kk * 8;
#pragma unroll
            for (int nt = 0; nt < 8; nt++) {
                const int vr = (nt * 8 + g) * A_STR;
                uint32_t b0 = Vs[vr + kl + tg];
                uint32_t b1 = Vs[vr + kl + tg + 4];
#pragma unroll
                for (int mt = 0; mt < 2; mt++)
                    mma_f16(o[mt][nt], af[mt][0], af[mt][1], af[mt][2],
                            af[mt][3], b0, b1);
            }
        }
    }

    // Write normalized output, fp16 [token][H]
#pragma unroll
    for (int mt = 0; mt < 2; mt++) {
        const int r0 = q0 + qbase + mt * 16 + g;
        const float inv0 = 1.0f / lrun[mt][0];
        const float inv1 = 1.0f / lrun[mt][1];
        uint32_t* O0 = (uint32_t*)(Out + (size_t)(bb * L_ + r0) * H_ + hh * D_);
        uint32_t* O1 = (uint32_t*)(Out + (size_t)(bb * L_ + r0 + 8) * H_ + hh * D_);
#pragma unroll
        for (int nt = 0; nt < 8; nt++) {
            const int ci = nt * 4 + tg;    // h2 index within 64-wide head
            O0[ci] = pack_h2(o[mt][nt][0] * inv0, o[mt][nt][1] * inv0);
            O1[ci] = pack_h2(o[mt][nt][2] * inv1, o[mt][nt][3] * inv1);
        }
    }
}

// ---------------------------------------------------------------------------
extern "C" void kernel_launch(void* const* d_in, const int* in_sizes, int n_in,
                              void* d_out, int out_size)
{
    (void)in_sizes; (void)n_in; (void)out_size;
    const float* x    = (const float*)d_in[0];
    const float* y    = (const float*)d_in[1];
    const float* bias = (const float*)d_in[2];
    const float* Wq   = (const float*)d_in[3];
    const float* Wk   = (const float*)d_in[4];
    const float* Wv   = (const float*)d_in[5];
    const float* Wo   = (const float*)d_in[6];
    float* out = (float*)d_out;

    __half *Qp, *Kp, *Vp, *Tp, *xh, *yh, *wqT, *wkT, *wvT, *woT;
    cudaGetSymbolAddress((void**)&Qp, g_Q);
    cudaGetSymbolAddress((void**)&Kp, g_K);
    cudaGetSymbolAddress((void**)&Vp, g_V);
    cudaGetSymbolAddress((void**)&Tp, g_T);
    cudaGetSymbolAddress((void**)&xh, g_xh);
    cudaGetSymbolAddress((void**)&yh, g_yh);
    cudaGetSymbolAddress((void**)&wqT, g_wqT);
    cudaGetSymbolAddress((void**)&wkT, g_wkT);
    cudaGetSymbolAddress((void**)&wvT, g_wvT);
    cudaGetSymbolAddress((void**)&woT, g_woT);

    cudaFuncSetAttribute(attn_h,
                         cudaFuncAttributeMaxDynamicSharedMemorySize, ATTN_SMEM);
    cudaFuncSetAttribute(qkv_gemm,
                         cudaFuncAttributeMaxDynamicSharedMemorySize, G_SMEM);
    cudaFuncSetAttribute(out_gemm,
                         cudaFuncAttributeMaxDynamicSharedMemorySize, G_SMEM);

    const float qscale = 1.0f / sqrtf((float)D_);

    cvt_xy<<<dim3(128, 1, 2), 256>>>(x, y, xh, yh);
    wtrans<<<dim3(32, 32, 4), 256>>>(Wq, Wk, Wv, Wo, wqT, wkT, wvT, woT);

    qkv_gemm<<<dim3(8, 32, 3), 128, G_SMEM>>>(xh, yh, wqT, wkT, wvT,
                                              Qp, Kp, Vp, qscale);

    attn_h<<<dim3(16, 32), 128, ATTN_SMEM>>>(Qp, Kp, Vp, bias, Tp);

    out_gemm<<<dim3(8, 32), 128, G_SMEM>>>(Tp, woT, out);
}